// round 10
// baseline (speedup 1.0000x reference)
#include <cuda_runtime.h>
#include <cuda_bf16.h>
#include <math.h>
#include <stdint.h>

#define D_MODEL 1024
#define S_LEN   2048
#define NHEAD   16
#define HDIM    64
#define MAXB    4
#define MMAX    (MAXB * S_LEN)

// ---------------- scratch (__device__ globals; no allocs allowed) ----------
__device__ __nv_bfloat16 g_xh [MMAX * D_MODEL];
__device__ __nv_bfloat16 g_xl [MMAX * D_MODEL];
__device__ __nv_bfloat16 g_aoh[MMAX * D_MODEL];
__device__ __nv_bfloat16 g_aol[MMAX * D_MODEL];
__device__ __nv_bfloat16 g_wh [4 * D_MODEL * D_MODEL];
__device__ __nv_bfloat16 g_wl [4 * D_MODEL * D_MODEL];
__device__ __nv_bfloat16 g_qh [MMAX * D_MODEL];
__device__ __nv_bfloat16 g_ql [MMAX * D_MODEL];
__device__ __nv_bfloat16 g_kh [MMAX * D_MODEL];
__device__ __nv_bfloat16 g_kl [MMAX * D_MODEL];
__device__ __nv_bfloat16 g_vh [MMAX * D_MODEL];
__device__ __nv_bfloat16 g_vl [MMAX * D_MODEL];
__device__ float g_ct[S_LEN * 32];
__device__ float g_st[S_LEN * 32];

// ---------------- helpers ----------------------------------------------------
__device__ __forceinline__ uint32_t smem_u32(const void* p) {
    uint32_t a;
    asm("{ .reg .u64 t; cvta.to.shared.u64 t, %1; cvt.u32.u64 %0, t; }" : "=r"(a) : "l"(p));
    return a;
}
__device__ __forceinline__ void cp_async16(uint32_t saddr, const void* gptr) {
    asm volatile("cp.async.cg.shared.global [%0], [%1], 16;" :: "r"(saddr), "l"(gptr));
}
__device__ __forceinline__ void ldmx4(uint32_t* r, uint32_t addr) {
    asm volatile("ldmatrix.sync.aligned.m8n8.x4.shared.b16 {%0,%1,%2,%3}, [%4];"
                 : "=r"(r[0]), "=r"(r[1]), "=r"(r[2]), "=r"(r[3]) : "r"(addr));
}
__device__ __forceinline__ void ldmx4t(uint32_t* r, uint32_t addr) {
    asm volatile("ldmatrix.sync.aligned.m8n8.x4.trans.shared.b16 {%0,%1,%2,%3}, [%4];"
                 : "=r"(r[0]), "=r"(r[1]), "=r"(r[2]), "=r"(r[3]) : "r"(addr));
}
__device__ __forceinline__ void mma16816(float* d, const uint32_t* a, const uint32_t* b) {
    asm volatile("mma.sync.aligned.m16n8k16.row.col.f32.bf16.bf16.f32 "
                 "{%0,%1,%2,%3}, {%4,%5,%6,%7}, {%8,%9}, {%0,%1,%2,%3};"
                 : "+f"(d[0]), "+f"(d[1]), "+f"(d[2]), "+f"(d[3])
                 : "r"(a[0]), "r"(a[1]), "r"(a[2]), "r"(a[3]), "r"(b[0]), "r"(b[1]));
}
__device__ __forceinline__ void store_split_pair(
    __nv_bfloat16* H, __nv_bfloat16* L, size_t off, float a, float b)
{
    __nv_bfloat162 hi = __float22bfloat162_rn(make_float2(a, b));
    __nv_bfloat162 lo = __float22bfloat162_rn(
        make_float2(a - __bfloat162float(hi.x), b - __bfloat162float(hi.y)));
    *(__nv_bfloat162*)(H + off) = hi;
    *(__nv_bfloat162*)(L + off) = lo;
}

// ---------------- split fp32 -> bf16 hi/lo ----------------------------------
__global__ void split_kernel(const float* __restrict__ X,
                             __nv_bfloat16* __restrict__ H,
                             __nv_bfloat16* __restrict__ L, int n4)
{
    int i = blockIdx.x * blockDim.x + threadIdx.x;
    if (i >= n4) return;
    float4 v = ((const float4*)X)[i];
    __nv_bfloat16 h0 = __float2bfloat16(v.x), h1 = __float2bfloat16(v.y);
    __nv_bfloat16 h2 = __float2bfloat16(v.z), h3 = __float2bfloat16(v.w);
    __nv_bfloat16 l0 = __float2bfloat16(v.x - __bfloat162float(h0));
    __nv_bfloat16 l1 = __float2bfloat16(v.y - __bfloat162float(h1));
    __nv_bfloat16 l2 = __float2bfloat16(v.z - __bfloat162float(h2));
    __nv_bfloat16 l3 = __float2bfloat16(v.w - __bfloat162float(h3));
    __nv_bfloat162 hA = {h0, h1}, hB = {h2, h3}, lA = {l0, l1}, lB = {l2, l3};
    uint2 hv, lv;
    hv.x = *(uint32_t*)&hA; hv.y = *(uint32_t*)&hB;
    lv.x = *(uint32_t*)&lA; lv.y = *(uint32_t*)&lB;
    ((uint2*)H)[i] = hv;
    ((uint2*)L)[i] = lv;
}

__global__ void split_w4(const float* __restrict__ W0, const float* __restrict__ W1,
                         const float* __restrict__ W2, const float* __restrict__ W3,
                         __nv_bfloat16* __restrict__ H, __nv_bfloat16* __restrict__ L,
                         int n4)
{
    int i = blockIdx.x * blockDim.x + threadIdx.x;
    if (i >= n4) return;
    int z = blockIdx.y;
    const float* X = (z == 0) ? W0 : (z == 1) ? W1 : (z == 2) ? W2 : W3;
    float4 v = ((const float4*)X)[i];
    __nv_bfloat16 h0 = __float2bfloat16(v.x), h1 = __float2bfloat16(v.y);
    __nv_bfloat16 h2 = __float2bfloat16(v.z), h3 = __float2bfloat16(v.w);
    __nv_bfloat16 l0 = __float2bfloat16(v.x - __bfloat162float(h0));
    __nv_bfloat16 l1 = __float2bfloat16(v.y - __bfloat162float(h1));
    __nv_bfloat16 l2 = __float2bfloat16(v.z - __bfloat162float(h2));
    __nv_bfloat16 l3 = __float2bfloat16(v.w - __bfloat162float(h3));
    __nv_bfloat162 hA = {h0, h1}, hB = {h2, h3}, lA = {l0, l1}, lB = {l2, l3};
    uint2 hv, lv;
    hv.x = *(uint32_t*)&hA; hv.y = *(uint32_t*)&hB;
    lv.x = *(uint32_t*)&lA; lv.y = *(uint32_t*)&lB;
    ((uint2*)(H + (size_t)z * D_MODEL * D_MODEL))[i] = hv;
    ((uint2*)(L + (size_t)z * D_MODEL * D_MODEL))[i] = lv;
}

// ---------------- RoPE cos/sin table ----------------------------------------
__global__ void rope_tab(float* __restrict__ ct, float* __restrict__ st)
{
    int idx = blockIdx.x * blockDim.x + threadIdx.x;
    if (idx >= S_LEN * 32) return;
    int s = idx >> 5, i = idx & 31;
    float inv = expf(-logf(10000.0f) * ((float)i / 32.0f));
    float sn, cs;
    sincosf((float)s * inv, &sn, &cs);
    ct[idx] = cs; st[idx] = sn;
}

// ---------------- GEMM core: 64x64 tile, 128 thr, 4 CTAs/SM ------------------
#define GSTRIDE 40
#define G2ARR   (64 * GSTRIDE * 2)       // 5120 B
#define G2BUF   (4 * G2ARR)              // 20480 B per stage
#define G2_SMEM (2 * G2BUF)              // 40960 B -> 4 CTAs/SM

// compute one 32-wide K chunk for a 64x64 tile; 4 warps (2x2), warp 32x32
__device__ __forceinline__ void gemm64_chunk(
    uint32_t boff, int lane, int warp_m, int warp_n, float acc[2][4][4])
{
    #pragma unroll
    for (int ks = 0; ks < 2; ++ks) {
        uint32_t ah[2][4], al[2][4];
        {
            const int arow = warp_m * 32 + (lane & 15);
            const int acol = ks * 16 + (lane >> 4) * 8;
            #pragma unroll
            for (int mi = 0; mi < 2; ++mi) {
                uint32_t addr = boff + (uint32_t)((arow + mi * 16) * GSTRIDE + acol) * 2;
                ldmx4(ah[mi], addr);
                ldmx4(al[mi], addr + G2ARR);
            }
        }
        const int brow_base = warp_n * 32 + ((lane >> 4) * 8) + (lane & 7);
        const int bcol = ks * 16 + ((lane >> 3) & 1) * 8;
        #pragma unroll
        for (int g = 0; g < 2; ++g) {
            uint32_t bh[2][2], bl[2][2];
            uint32_t addr = boff + 2 * G2ARR +
                            (uint32_t)((brow_base + g * 16) * GSTRIDE + bcol) * 2;
            uint32_t r[4];
            ldmx4(r, addr);
            bh[0][0] = r[0]; bh[0][1] = r[1]; bh[1][0] = r[2]; bh[1][1] = r[3];
            ldmx4(r, addr + G2ARR);
            bl[0][0] = r[0]; bl[0][1] = r[1]; bl[1][0] = r[2]; bl[1][1] = r[3];
            #pragma unroll
            for (int mi = 0; mi < 2; ++mi)
                #pragma unroll
                for (int nn = 0; nn < 2; ++nn) {
                    float* a = acc[mi][g * 2 + nn];
                    mma16816(a, ah[mi], bh[nn]);
                    mma16816(a, ah[mi], bl[nn]);
                    mma16816(a, al[mi], bh[nn]);
                }
        }
    }
}

// load one 32-wide K chunk of A/B hi/lo tiles (64 rows each) with 128 threads
__device__ __forceinline__ void gemm64_load(
    uint32_t boff, int tid, int m0, int n0, int K, int k0,
    const __nv_bfloat16* __restrict__ Ah, const __nv_bfloat16* __restrict__ Al,
    const __nv_bfloat16* __restrict__ Bh, const __nv_bfloat16* __restrict__ Bl)
{
    const __nv_bfloat16* srcs[4] = {Ah, Al, Bh, Bl};
    #pragma unroll
    for (int p = 0; p < 4; ++p) {
        const __nv_bfloat16* src = srcs[p];
        const int r0 = (p < 2) ? m0 : n0;
        const uint32_t abase = boff + (uint32_t)p * G2ARR;
        #pragma unroll
        for (int t = 0; t < 2; ++t) {
            int u = tid + t * 128;
            int row = u >> 2, c = (u & 3) * 8;
            cp_async16(abase + (uint32_t)(row * GSTRIDE + c) * 2,
                       src + (size_t)(r0 + row) * K + k0 + c);
        }
    }
    asm volatile("cp.async.commit_group;" ::: "memory");
}

// ---------------- fused QKV mega-GEMM (64x64 tiles) ---------------------------
__global__ __launch_bounds__(128, 4) void gemm_qkv(
    const __nv_bfloat16* __restrict__ Ah, const __nv_bfloat16* __restrict__ Al,
    const __nv_bfloat16* __restrict__ Wh, const __nv_bfloat16* __restrict__ Wl,
    __nv_bfloat16* __restrict__ Qh, __nv_bfloat16* __restrict__ Ql,
    __nv_bfloat16* __restrict__ Kh, __nv_bfloat16* __restrict__ Kl,
    __nv_bfloat16* __restrict__ Vh, __nv_bfloat16* __restrict__ Vl,
    const float* __restrict__ ct, const float* __restrict__ st,
    int M, int N, int K)
{
    extern __shared__ char smem[];
    const uint32_t sb = smem_u32(smem);
    const int tid = threadIdx.x;
    const int lane = tid & 31;
    const int wid = tid >> 5;
    const int warp_m = wid >> 1;
    const int warp_n = wid & 1;
    const int m0 = blockIdx.y * 64, n0 = blockIdx.x * 64;
    const int z = blockIdx.z;

    const __nv_bfloat16* Bh = Wh + (size_t)z * K * N;
    const __nv_bfloat16* Bl = Wl + (size_t)z * K * N;

    float acc[2][4][4] = {};

    gemm64_load(sb, tid, m0, n0, K, 0, Ah, Al, Bh, Bl);

    const int nch = K / 32;
    for (int c = 0; c < nch; ++c) {
        if (c + 1 < nch) {
            gemm64_load(sb + (uint32_t)((c + 1) & 1) * G2BUF, tid, m0, n0, K,
                        (c + 1) * 32, Ah, Al, Bh, Bl);
            asm volatile("cp.async.wait_group 1;" ::: "memory");
        } else {
            asm volatile("cp.async.wait_group 0;" ::: "memory");
        }
        __syncthreads();
        gemm64_chunk(sb + (uint32_t)(c & 1) * G2BUF, lane, warp_m, warp_n, acc);
        __syncthreads();
    }

    __nv_bfloat16* H = (z == 0) ? Qh : (z == 1) ? Kh : Vh;
    __nv_bfloat16* L = (z == 0) ? Ql : (z == 1) ? Kl : Vl;
    const float qscale = (z == 0) ? 0.125f : 1.0f;

    #pragma unroll
    for (int mi = 0; mi < 2; ++mi) {
        const int r = m0 + warp_m * 32 + mi * 16 + (lane >> 2);
        const int s0 = r & (S_LEN - 1);
        const int s1 = (r + 8) & (S_LEN - 1);
        #pragma unroll
        for (int ni = 0; ni < 4; ++ni) {
            const int cidx = n0 + warp_n * 32 + ni * 8 + (lane & 3) * 2;
            float a0 = acc[mi][ni][0], a1 = acc[mi][ni][1];
            float b0 = acc[mi][ni][2], b1 = acc[mi][ni][3];
            if (z < 2) {
                const int i = (cidx & (HDIM - 1)) >> 1;
                float c0 = ct[s0 * 32 + i], sn0 = st[s0 * 32 + i];
                float c1 = ct[s1 * 32 + i], sn1 = st[s1 * 32 + i];
                float e = a0, o = a1;
                a0 = (e * c0 - o * sn0) * qscale;
                a1 = (e * sn0 + o * c0) * qscale;
                e = b0; o = b1;
                b0 = (e * c1 - o * sn1) * qscale;
                b1 = (e * sn1 + o * c1) * qscale;
            }
            store_split_pair(H, L, (size_t)r * N + cidx, a0, a1);
            store_split_pair(H, L, (size_t)(r + 8) * N + cidx, b0, b1);
        }
    }
}

// ---------------- plain GEMM (final O-proj, 64x64 tiles) ----------------------
__global__ __launch_bounds__(128, 4) void gemm_mma(
    const __nv_bfloat16* __restrict__ Ah, const __nv_bfloat16* __restrict__ Al,
    const __nv_bfloat16* __restrict__ Bh, const __nv_bfloat16* __restrict__ Bl,
    float* __restrict__ C, int M, int N, int K)
{
    extern __shared__ char smem[];
    const uint32_t sb = smem_u32(smem);
    const int tid = threadIdx.x;
    const int lane = tid & 31;
    const int wid = tid >> 5;
    const int warp_m = wid >> 1;
    const int warp_n = wid & 1;
    const int m0 = blockIdx.y * 64, n0 = blockIdx.x * 64;

    float acc[2][4][4] = {};

    gemm64_load(sb, tid, m0, n0, K, 0, Ah, Al, Bh, Bl);

    const int nch = K / 32;
    for (int c = 0; c < nch; ++c) {
        if (c + 1 < nch) {
            gemm64_load(sb + (uint32_t)((c + 1) & 1) * G2BUF, tid, m0, n0, K,
                        (c + 1) * 32, Ah, Al, Bh, Bl);
            asm volatile("cp.async.wait_group 1;" ::: "memory");
        } else {
            asm volatile("cp.async.wait_group 0;" ::: "memory");
        }
        __syncthreads();
        gemm64_chunk(sb + (uint32_t)(c & 1) * G2BUF, lane, warp_m, warp_n, acc);
        __syncthreads();
    }

    #pragma unroll
    for (int mi = 0; mi < 2; ++mi) {
        const int r = m0 + warp_m * 32 + mi * 16 + (lane >> 2);
        #pragma unroll
        for (int ni = 0; ni < 4; ++ni) {
            const int cidx = n0 + warp_n * 32 + ni * 8 + (lane & 3) * 2;
            float2 v0 = {acc[mi][ni][0], acc[mi][ni][1]};
            float2 v1 = {acc[mi][ni][2], acc[mi][ni][3]};
            *(float2*)(C + (size_t)r * N + cidx)       = v0;
            *(float2*)(C + (size_t)(r + 8) * N + cidx) = v1;
        }
    }
}

// ---------------- HMMA split-bf16 causal flash attention --------------------
// q-block 256, 8 warps x m32. Q in smem (hi/lo), KV 3-stage cp.async ring.
#define FSTR   72
#define FARR   (64 * FSTR * 2)          // 9216 B
#define FSTAGE (4 * FARR)               // 36864 B (Kh,Kl,Vh,Vl)
#define FQARR  (256 * FSTR * 2)         // 36864 B
#define FKVOFF (2 * FQARR)              // 73728
#define F_SMEM (FKVOFF + 3 * FSTAGE)    // 184320 B

__global__ __launch_bounds__(256, 1) void flash_mma(
    const __nv_bfloat16* __restrict__ Qh_, const __nv_bfloat16* __restrict__ Ql_,
    const __nv_bfloat16* __restrict__ Kh_, const __nv_bfloat16* __restrict__ Kl_,
    const __nv_bfloat16* __restrict__ Vh_, const __nv_bfloat16* __restrict__ Vl_,
    __nv_bfloat16* __restrict__ AOh, __nv_bfloat16* __restrict__ AOl)
{
    extern __shared__ char smem[];
    const uint32_t sb = smem_u32(smem);
    const int tid = threadIdx.x, lane = tid & 31, w = tid >> 5;
    const int b = blockIdx.z, h = blockIdx.y, q0 = blockIdx.x * 256;

    const size_t base_q = (size_t)(b * S_LEN + q0) * D_MODEL + h * HDIM;

    #pragma unroll
    for (int t = 0; t < 8; ++t) {
        int idx = tid + t * 256;
        int r = idx >> 3, c = (idx & 7) * 8;
        cp_async16(sb + (uint32_t)(r * FSTR + c) * 2, Qh_ + base_q + (size_t)r * D_MODEL + c);
        cp_async16(sb + FQARR + (uint32_t)(r * FSTR + c) * 2,
                   Ql_ + base_q + (size_t)r * D_MODEL + c);
    }
    asm volatile("cp.async.commit_group;" ::: "memory");

    const __nv_bfloat16* kv_src[4] = {Kh_, Kl_, Vh_, Vl_};
    auto load_kv = [&](int j, int st) {
        const size_t gb = (size_t)(b * S_LEN + j * 64) * D_MODEL + h * HDIM;
        const uint32_t sbase = sb + FKVOFF + (uint32_t)st * FSTAGE;
        #pragma unroll
        for (int p = 0; p < 4; ++p) {
            #pragma unroll
            for (int t = 0; t < 2; ++t) {
                int idx = tid + t * 256;
                int r = idx >> 3, c = (idx & 7) * 8;
                cp_async16(sbase + (uint32_t)p * FARR + (uint32_t)(r * FSTR + c) * 2,
                           kv_src[p] + gb + (size_t)r * D_MODEL + c);
            }
        }
        asm volatile("cp.async.commit_group;" ::: "memory");
    };

    const int jend = 4 * blockIdx.x + 4;
    load_kv(0, 0);
    if (jend > 1) load_kv(1, 1);

    float o[2][8][4] = {};
    float mrow[2][2] = {{-1e30f, -1e30f}, {-1e30f, -1e30f}};
    float lrow[2][2] = {};

    for (int j = 0; j < jend; ++j) {
        if (j + 1 < jend) {
            asm volatile("cp.async.wait_group 1;" ::: "memory");
        } else {
            asm volatile("cp.async.wait_group 0;" ::: "memory");
        }
        __syncthreads();
        if (j + 2 < jend) load_kv(j + 2, (j + 2) % 3);

        const int k0 = j * 64;
        if (k0 <= q0 + w * 32 + 31) {
            const uint32_t sbase = sb + FKVOFF + (uint32_t)(j % 3) * FSTAGE;

            float s[2][8][4] = {};
            #pragma unroll
            for (int ks = 0; ks < 4; ++ks) {
                uint32_t bh[8][2], bl[8][2];
                #pragma unroll
                for (int g = 0; g < 4; ++g) {
                    const int row = g * 16 + (lane >> 4) * 8 + (lane & 7);
                    const int col = ks * 16 + ((lane >> 3) & 1) * 8;
                    uint32_t addr = sbase + (uint32_t)(row * FSTR + col) * 2;
                    uint32_t r4[4];
                    ldmx4(r4, addr);
                    bh[2*g][0]=r4[0]; bh[2*g][1]=r4[1]; bh[2*g+1][0]=r4[2]; bh[2*g+1][1]=r4[3];
                    ldmx4(r4, addr + FARR);
                    bl[2*g][0]=r4[0]; bl[2*g][1]=r4[1]; bl[2*g+1][0]=r4[2]; bl[2*g+1][1]=r4[3];
                }
                #pragma unroll
                for (int mf = 0; mf < 2; ++mf) {
                    const int qrow = w * 32 + mf * 16 + (lane & 15);
                    const int qcol = ks * 16 + (lane >> 4) * 8;
                    uint32_t qaddr = sb + (uint32_t)(qrow * FSTR + qcol) * 2;
                    uint32_t qhf[4], qlf[4];
                    ldmx4(qhf, qaddr);
                    ldmx4(qlf, qaddr + FQARR);
                    #pragma unroll
                    for (int n = 0; n < 8; ++n) mma16816(s[mf][n], qhf, bh[n]);
                    #pragma unroll
                    for (int n = 0; n < 8; ++n) mma16816(s[mf][n], qhf, bl[n]);
                    #pragma unroll
                    for (int n = 0; n < 8; ++n) mma16816(s[mf][n], qlf, bh[n]);
                }
            }

            uint32_t ph[2][2][8];
            float a[2][2];
            #pragma unroll
            for (int mf = 0; mf < 2; ++mf) {
                const int gr = q0 + w * 32 + mf * 16 + (lane >> 2);
                if (k0 + 63 > q0 + w * 32 + mf * 16) {
                    #pragma unroll
                    for (int t = 0; t < 8; ++t) {
                        int c = k0 + t * 8 + 2 * (lane & 3);
                        if (c     > gr)     s[mf][t][0] = -1e30f;
                        if (c + 1 > gr)     s[mf][t][1] = -1e30f;
                        if (c     > gr + 8) s[mf][t][2] = -1e30f;
                        if (c + 1 > gr + 8) s[mf][t][3] = -1e30f;
                    }
                }
                float mx0 = -1e30f, mx1 = -1e30f;
                #pragma unroll
                for (int t = 0; t < 8; ++t) {
                    mx0 = fmaxf(mx0, fmaxf(s[mf][t][0], s[mf][t][1]));
                    mx1 = fmaxf(mx1, fmaxf(s[mf][t][2], s[mf][t][3]));
                }
                mx0 = fmaxf(mx0, __shfl_xor_sync(0xffffffffu, mx0, 1));
                mx0 = fmaxf(mx0, __shfl_xor_sync(0xffffffffu, mx0, 2));
                mx1 = fmaxf(mx1, __shfl_xor_sync(0xffffffffu, mx1, 1));
                mx1 = fmaxf(mx1, __shfl_xor_sync(0xffffffffu, mx1, 2));
                const float mn0 = fmaxf(mrow[mf][0], mx0), mn1 = fmaxf(mrow[mf][1], mx1);
                a[mf][0] = __expf(mrow[mf][0] - mn0);
                a[mf][1] = __expf(mrow[mf][1] - mn1);
                mrow[mf][0] = mn0; mrow[mf][1] = mn1;

                float ps0 = 0.0f, ps1 = 0.0f;
                #pragma unroll
                for (int t = 0; t < 8; ++t) {
                    float p0 = __expf(s[mf][t][0] - mn0), p1 = __expf(s[mf][t][1] - mn0);
                    float p2 = __expf(s[mf][t][2] - mn1), p3 = __expf(s[mf][t][3] - mn1);
                    ps0 += p0 + p1; ps1 += p2 + p3;
                    __nv_bfloat162 h01 = __float22bfloat162_rn(make_float2(p0, p1));
                    __nv_bfloat162 h23 = __float22bfloat162_rn(make_float2(p2, p3));
                    ph[mf][0][t] = *(uint32_t*)&h01;
                    ph[mf][1][t] = *(uint32_t*)&h23;
                }
                ps0 += __shfl_xor_sync(0xffffffffu, ps0, 1);
                ps0 += __shfl_xor_sync(0xffffffffu, ps0, 2);
                ps1 += __shfl_xor_sync(0xffffffffu, ps1, 1);
                ps1 += __shfl_xor_sync(0xffffffffu, ps1, 2);
                lrow[mf][0] = lrow[mf][0] * a[mf][0] + ps0;
                lrow[mf][1] = lrow[mf][1] * a[mf][1] + ps1;

                #pragma unroll
                for (int t = 0; t < 8; ++t) {
                    o[mf][t][0] *= a[mf][0]; o[mf][t][1] *= a[mf][0];
                    o[mf][t][2] *= a[mf][1]; o[mf][t][3] *= a[mf][1];
                }
            }

            #pragma unroll
            for (int ks = 0; ks < 4; ++ks) {
                uint32_t bvh[8][2], bvl[8][2];
                #pragma unroll
                for (int g = 0; g < 4; ++g) {
                    const int row = ks * 16 + (lane & 15);
                    const int col = g * 16 + (lane >> 4) * 8;
                    uint32_t addr = sbase + 2u * FARR + (uint32_t)(row * FSTR + col) * 2;
                    uint32_t r4[4];
                    ldmx4t(r4, addr);
                    bvh[2*g][0]=r4[0]; bvh[2*g][1]=r4[1]; bvh[2*g+1][0]=r4[2]; bvh[2*g+1][1]=r4[3];
                    ldmx4t(r4, addr + FARR);
                    bvl[2*g][0]=r4[0]; bvl[2*g][1]=r4[1]; bvl[2*g+1][0]=r4[2]; bvl[2*g+1][1]=r4[3];
                }
                #pragma unroll
                for (int mf = 0; mf < 2; ++mf) {
                    uint32_t pah[4] = {ph[mf][0][2*ks], ph[mf][1][2*ks],
                                       ph[mf][0][2*ks+1], ph[mf][1][2*ks+1]};
                    #pragma unroll
                    for (int n = 0; n < 8; ++n) mma16816(o[mf][n], pah, bvh[n]);
                    #pragma unroll
                    for (int n = 0; n < 8; ++n) mma16816(o[mf][n], pah, bvl[n]);
                }
            }
        }
    }

    const size_t ob = (size_t)b * S_LEN * D_MODEL + h * HDIM;
    #pragma unroll
    for (int mf = 0; mf < 2; ++mf) {
        const float inv0 = 1.0f / lrow[mf][0], inv1 = 1.0f / lrow[mf][1];
        const int gr = q0 + w * 32 + mf * 16 + (lane >> 2);
        #pragma unroll
        for (int t = 0; t < 8; ++t) {
            const int c = t * 8 + 2 * (lane & 3);
            store_split_pair(AOh, AOl, ob + (size_t)gr * D_MODEL + c,
                             o[mf][t][0] * inv0, o[mf][t][1] * inv0);
            store_split_pair(AOh, AOl, ob + (size_t)(gr + 8) * D_MODEL + c,
                             o[mf][t][2] * inv1, o[mf][t][3] * inv1);
        }
    }
}

// ---------------------------------------------------------------------------
extern "C" void kernel_launch(void* const* d_in, const int* in_sizes, int n_in,
                              void* d_out, int out_size)
{
    const float* x  = (const float*)d_in[0];
    const float* qw = (const float*)d_in[1];
    const float* kw = (const float*)d_in[2];
    const float* vw = (const float*)d_in[3];
    const float* ow = (const float*)d_in[4];

    const int M = in_sizes[0] / D_MODEL;
    const int B = M / S_LEN;
    const int W = D_MODEL * D_MODEL;

    void *pxh, *pxl, *pah, *pal, *pwh, *pwl;
    void *pqh, *pql, *pkh, *pkl, *pvh, *pvl, *pct, *pst;
    cudaGetSymbolAddress(&pxh, g_xh);  cudaGetSymbolAddress(&pxl, g_xl);
    cudaGetSymbolAddress(&pah, g_aoh); cudaGetSymbolAddress(&pal, g_aol);
    cudaGetSymbolAddress(&pwh, g_wh);  cudaGetSymbolAddress(&pwl, g_wl);
    cudaGetSymbolAddress(&pqh, g_qh);  cudaGetSymbolAddress(&pql, g_ql);
    cudaGetSymbolAddress(&pkh, g_kh);  cudaGetSymbolAddress(&pkl, g_kl);
    cudaGetSymbolAddress(&pvh, g_vh);  cudaGetSymbolAddress(&pvl, g_vl);
    cudaGetSymbolAddress(&pct, g_ct);  cudaGetSymbolAddress(&pst, g_st);
    __nv_bfloat16* xh = (__nv_bfloat16*)pxh;  __nv_bfloat16* xl = (__nv_bfloat16*)pxl;
    __nv_bfloat16* aoh = (__nv_bfloat16*)pah; __nv_bfloat16* aol = (__nv_bfloat16*)pal;
    __nv_bfloat16* wh = (__nv_bfloat16*)pwh;  __nv_bfloat16* wl = (__nv_bfloat16*)pwl;
    __nv_bfloat16* qhp = (__nv_bfloat16*)pqh; __nv_bfloat16* qlp = (__nv_bfloat16*)pql;
    __nv_bfloat16* khp = (__nv_bfloat16*)pkh; __nv_bfloat16* klp = (__nv_bfloat16*)pkl;
    __nv_bfloat16* vhp = (__nv_bfloat16*)pvh; __nv_bfloat16* vlp = (__nv_bfloat16*)pvl;
    float* ct = (float*)pct; float* st = (float*)pst;

    int n4x = M * D_MODEL / 4;
    split_kernel<<<(n4x + 255) / 256, 256>>>(x, xh, xl, n4x);
    int n4w = W / 4;
    dim3 wgrid((n4w + 255) / 256, 4);
    split_w4<<<wgrid, 256>>>(qw, kw, vw, ow, wh, wl, n4w);
    rope_tab<<<(S_LEN * 32 + 255) / 256, 256>>>(ct, st);

    cudaFuncSetAttribute(gemm_qkv, cudaFuncAttributeMaxDynamicSharedMemorySize, G2_SMEM);
    dim3 qkvgrid(D_MODEL / 64, M / 64, 3);
    gemm_qkv<<<qkvgrid, 128, G2_SMEM>>>(xh, xl, wh, wl,
                                        qhp, qlp, khp, klp, vhp, vlp,
                                        ct, st, M, D_MODEL, D_MODEL);

    cudaFuncSetAttribute(flash_mma, cudaFuncAttributeMaxDynamicSharedMemorySize, F_SMEM);
    dim3 fgrid(S_LEN / 256, NHEAD, B);
    flash_mma<<<fgrid, 256, F_SMEM>>>(qhp, qlp, khp, klp, vhp, vlp, aoh, aol);

    cudaFuncSetAttribute(gemm_mma, cudaFuncAttributeMaxDynamicSharedMemorySize, G2_SMEM);
    dim3 ggrid(D_MODEL / 64, M / 64);
    gemm_mma<<<ggrid, 128, G2_SMEM>>>(aoh, aol, wh + 3 * W, wl + 3 * W,
                                      (float*)d_out, M, D_MODEL, D_MODEL);
}

// round 12
// speedup vs baseline: 1.0530x; 1.0530x over previous
#include <cuda_runtime.h>
#include <cuda_bf16.h>
#include <math.h>
#include <stdint.h>

#define D_MODEL 1024
#define S_LEN   2048
#define NHEAD   16
#define HDIM    64
#define MAXB    4
#define MMAX    (MAXB * S_LEN)

// ---------------- scratch (__device__ globals; no allocs allowed) ----------
__device__ __nv_bfloat16 g_xh [MMAX * D_MODEL];
__device__ __nv_bfloat16 g_xl [MMAX * D_MODEL];
__device__ __nv_bfloat16 g_aoh[MMAX * D_MODEL];
__device__ __nv_bfloat16 g_aol[MMAX * D_MODEL];
__device__ __nv_bfloat16 g_wh [4 * D_MODEL * D_MODEL];
__device__ __nv_bfloat16 g_wl [4 * D_MODEL * D_MODEL];
__device__ __nv_bfloat16 g_qh [MMAX * D_MODEL];
__device__ __nv_bfloat16 g_ql [MMAX * D_MODEL];
__device__ __nv_bfloat16 g_kh [MMAX * D_MODEL];
__device__ __nv_bfloat16 g_kl [MMAX * D_MODEL];
__device__ __nv_bfloat16 g_vh [MMAX * D_MODEL];
__device__ __nv_bfloat16 g_vl [MMAX * D_MODEL];
__device__ float g_ct[S_LEN * 32];
__device__ float g_st[S_LEN * 32];

// ---------------- helpers ----------------------------------------------------
__device__ __forceinline__ uint32_t smem_u32(const void* p) {
    uint32_t a;
    asm("{ .reg .u64 t; cvta.to.shared.u64 t, %1; cvt.u32.u64 %0, t; }" : "=r"(a) : "l"(p));
    return a;
}
__device__ __forceinline__ void cp_async16(uint32_t saddr, const void* gptr) {
    asm volatile("cp.async.cg.shared.global [%0], [%1], 16;" :: "r"(saddr), "l"(gptr));
}
__device__ __forceinline__ void ldmx4(uint32_t* r, uint32_t addr) {
    asm volatile("ldmatrix.sync.aligned.m8n8.x4.shared.b16 {%0,%1,%2,%3}, [%4];"
                 : "=r"(r[0]), "=r"(r[1]), "=r"(r[2]), "=r"(r[3]) : "r"(addr));
}
__device__ __forceinline__ void ldmx4t(uint32_t* r, uint32_t addr) {
    asm volatile("ldmatrix.sync.aligned.m8n8.x4.trans.shared.b16 {%0,%1,%2,%3}, [%4];"
                 : "=r"(r[0]), "=r"(r[1]), "=r"(r[2]), "=r"(r[3]) : "r"(addr));
}
__device__ __forceinline__ void mma16816(float* d, const uint32_t* a, const uint32_t* b) {
    asm volatile("mma.sync.aligned.m16n8k16.row.col.f32.bf16.bf16.f32 "
                 "{%0,%1,%2,%3}, {%4,%5,%6,%7}, {%8,%9}, {%0,%1,%2,%3};"
                 : "+f"(d[0]), "+f"(d[1]), "+f"(d[2]), "+f"(d[3])
                 : "r"(a[0]), "r"(a[1]), "r"(a[2]), "r"(a[3]), "r"(b[0]), "r"(b[1]));
}
__device__ __forceinline__ void store_split_pair(
    __nv_bfloat16* H, __nv_bfloat16* L, size_t off, float a, float b)
{
    __nv_bfloat162 hi = __float22bfloat162_rn(make_float2(a, b));
    __nv_bfloat162 lo = __float22bfloat162_rn(
        make_float2(a - __bfloat162float(hi.x), b - __bfloat162float(hi.y)));
    *(__nv_bfloat162*)(H + off) = hi;
    *(__nv_bfloat162*)(L + off) = lo;
}

// ---------------- split fp32 -> bf16 hi/lo ----------------------------------
__global__ void split_kernel(const float* __restrict__ X,
                             __nv_bfloat16* __restrict__ H,
                             __nv_bfloat16* __restrict__ L, int n4)
{
    int i = blockIdx.x * blockDim.x + threadIdx.x;
    if (i >= n4) return;
    float4 v = ((const float4*)X)[i];
    __nv_bfloat16 h0 = __float2bfloat16(v.x), h1 = __float2bfloat16(v.y);
    __nv_bfloat16 h2 = __float2bfloat16(v.z), h3 = __float2bfloat16(v.w);
    __nv_bfloat16 l0 = __float2bfloat16(v.x - __bfloat162float(h0));
    __nv_bfloat16 l1 = __float2bfloat16(v.y - __bfloat162float(h1));
    __nv_bfloat16 l2 = __float2bfloat16(v.z - __bfloat162float(h2));
    __nv_bfloat16 l3 = __float2bfloat16(v.w - __bfloat162float(h3));
    __nv_bfloat162 hA = {h0, h1}, hB = {h2, h3}, lA = {l0, l1}, lB = {l2, l3};
    uint2 hv, lv;
    hv.x = *(uint32_t*)&hA; hv.y = *(uint32_t*)&hB;
    lv.x = *(uint32_t*)&lA; lv.y = *(uint32_t*)&lB;
    ((uint2*)H)[i] = hv;
    ((uint2*)L)[i] = lv;
}

__global__ void split_w4(const float* __restrict__ W0, const float* __restrict__ W1,
                         const float* __restrict__ W2, const float* __restrict__ W3,
                         __nv_bfloat16* __restrict__ H, __nv_bfloat16* __restrict__ L,
                         int n4)
{
    int i = blockIdx.x * blockDim.x + threadIdx.x;
    if (i >= n4) return;
    int z = blockIdx.y;
    const float* X = (z == 0) ? W0 : (z == 1) ? W1 : (z == 2) ? W2 : W3;
    float4 v = ((const float4*)X)[i];
    __nv_bfloat16 h0 = __float2bfloat16(v.x), h1 = __float2bfloat16(v.y);
    __nv_bfloat16 h2 = __float2bfloat16(v.z), h3 = __float2bfloat16(v.w);
    __nv_bfloat16 l0 = __float2bfloat16(v.x - __bfloat162float(h0));
    __nv_bfloat16 l1 = __float2bfloat16(v.y - __bfloat162float(h1));
    __nv_bfloat16 l2 = __float2bfloat16(v.z - __bfloat162float(h2));
    __nv_bfloat16 l3 = __float2bfloat16(v.w - __bfloat162float(h3));
    __nv_bfloat162 hA = {h0, h1}, hB = {h2, h3}, lA = {l0, l1}, lB = {l2, l3};
    uint2 hv, lv;
    hv.x = *(uint32_t*)&hA; hv.y = *(uint32_t*)&hB;
    lv.x = *(uint32_t*)&lA; lv.y = *(uint32_t*)&lB;
    ((uint2*)(H + (size_t)z * D_MODEL * D_MODEL))[i] = hv;
    ((uint2*)(L + (size_t)z * D_MODEL * D_MODEL))[i] = lv;
}

// ---------------- RoPE cos/sin table ----------------------------------------
__global__ void rope_tab(float* __restrict__ ct, float* __restrict__ st)
{
    int idx = blockIdx.x * blockDim.x + threadIdx.x;
    if (idx >= S_LEN * 32) return;
    int s = idx >> 5, i = idx & 31;
    float inv = expf(-logf(10000.0f) * ((float)i / 32.0f));
    float sn, cs;
    sincosf((float)s * inv, &sn, &cs);
    ct[idx] = cs; st[idx] = sn;
}

// ---------------- GEMM core: 128x128, 2-stage ring, ONE sync per chunk ------
#define GSTRIDE 40
#define GARR    (128 * GSTRIDE * 2)      // 10240 B
#define GBUF    (4 * GARR)               // 40960 B per stage
#define G_SMEM_SZ (2 * GBUF)             // 81920 B -> 2 CTAs/SM

// compute one 32-wide K chunk; B frags all up front, A in two mi-halves
__device__ __forceinline__ void gemm_chunk_compute(
    uint32_t boff, int lane, int warp_m, int warp_n, float acc[4][4][4])
{
    const int arow = warp_m * 64 + (lane & 15);
    const int brow_base = warp_n * 32 + ((lane >> 4) * 8) + (lane & 7);
    #pragma unroll
    for (int ks = 0; ks < 2; ++ks) {
        const int acol = ks * 16 + (lane >> 4) * 8;
        const int bcol = ks * 16 + ((lane >> 3) & 1) * 8;
        uint32_t bh[4][2], bl[4][2];
        #pragma unroll
        for (int g = 0; g < 2; ++g) {
            uint32_t addr = boff + 2 * GARR +
                            (uint32_t)((brow_base + g * 16) * GSTRIDE + bcol) * 2;
            uint32_t r[4];
            ldmx4(r, addr);
            bh[2*g][0] = r[0]; bh[2*g][1] = r[1];
            bh[2*g+1][0] = r[2]; bh[2*g+1][1] = r[3];
            ldmx4(r, addr + GARR);
            bl[2*g][0] = r[0]; bl[2*g][1] = r[1];
            bl[2*g+1][0] = r[2]; bl[2*g+1][1] = r[3];
        }
        #pragma unroll
        for (int half = 0; half < 2; ++half) {
            uint32_t ah[2][4], al[2][4];
            #pragma unroll
            for (int mi = 0; mi < 2; ++mi) {
                uint32_t addr = boff +
                    (uint32_t)((arow + (half * 2 + mi) * 16) * GSTRIDE + acol) * 2;
                ldmx4(ah[mi], addr);
                ldmx4(al[mi], addr + GARR);
            }
            #pragma unroll
            for (int mi = 0; mi < 2; ++mi)
                #pragma unroll
                for (int ni = 0; ni < 4; ++ni) {
                    float* a = acc[half * 2 + mi][ni];
                    mma16816(a, ah[mi], bh[ni]);
                    mma16816(a, ah[mi], bl[ni]);
                    mma16816(a, al[mi], bh[ni]);
                }
        }
    }
}

// ---------------- fused QKV mega-GEMM ----------------------------------------
__global__ __launch_bounds__(256, 2) void gemm_qkv(
    const __nv_bfloat16* __restrict__ Ah, const __nv_bfloat16* __restrict__ Al,
    const __nv_bfloat16* __restrict__ Wh, const __nv_bfloat16* __restrict__ Wl,
    __nv_bfloat16* __restrict__ Qh, __nv_bfloat16* __restrict__ Ql,
    __nv_bfloat16* __restrict__ Kh, __nv_bfloat16* __restrict__ Kl,
    __nv_bfloat16* __restrict__ Vh, __nv_bfloat16* __restrict__ Vl,
    const float* __restrict__ ct, const float* __restrict__ st,
    int M, int N, int K)
{
    extern __shared__ char smem[];
    const uint32_t sb = smem_u32(smem);
    const int tid = threadIdx.x;
    const int lane = tid & 31;
    const int wid = tid >> 5;
    const int warp_m = wid >> 2;
    const int warp_n = wid & 3;
    const int m0 = blockIdx.y * 128, n0 = blockIdx.x * 128;
    const int z = blockIdx.z;

    const __nv_bfloat16* Bh = Wh + (size_t)z * K * N;
    const __nv_bfloat16* Bl = Wl + (size_t)z * K * N;

    float acc[4][4][4] = {};
    const __nv_bfloat16* srcs[4] = {Ah, Al, Bh, Bl};

    auto load_chunk = [&](int k0, int buf) {
        const uint32_t boff = sb + (uint32_t)buf * GBUF;
        #pragma unroll
        for (int p = 0; p < 4; ++p) {
            const __nv_bfloat16* src = srcs[p];
            const int r0 = (p < 2) ? m0 : n0;
            const uint32_t abase = boff + (uint32_t)p * GARR;
            #pragma unroll
            for (int t = 0; t < 2; ++t) {
                int u = tid + t * 256;
                int row = u >> 2, c = (u & 3) * 8;
                cp_async16(abase + (uint32_t)(row * GSTRIDE + c) * 2,
                           src + (size_t)(r0 + row) * K + k0 + c);
            }
        }
        asm volatile("cp.async.commit_group;" ::: "memory");
    };

    load_chunk(0, 0);

    const int nch = K / 32;
    for (int c = 0; c < nch; ++c) {
        asm volatile("cp.async.wait_group 0;" ::: "memory");  // load(c) complete
        __syncthreads();                                      // + prior reads done
        if (c + 1 < nch) load_chunk((c + 1) * 32, (c + 1) & 1);
        gemm_chunk_compute(sb + (uint32_t)(c & 1) * GBUF, lane, warp_m, warp_n, acc);
    }

    __nv_bfloat16* H = (z == 0) ? Qh : (z == 1) ? Kh : Vh;
    __nv_bfloat16* L = (z == 0) ? Ql : (z == 1) ? Kl : Vl;
    const float qscale = (z == 0) ? 0.125f : 1.0f;

    #pragma unroll
    for (int mi = 0; mi < 4; ++mi) {
        const int r = m0 + warp_m * 64 + mi * 16 + (lane >> 2);
        const int s0 = r & (S_LEN - 1);
        const int s1 = (r + 8) & (S_LEN - 1);
        #pragma unroll
        for (int ni = 0; ni < 4; ++ni) {
            const int cidx = n0 + warp_n * 32 + ni * 8 + (lane & 3) * 2;
            float a0 = acc[mi][ni][0], a1 = acc[mi][ni][1];
            float b0 = acc[mi][ni][2], b1 = acc[mi][ni][3];
            if (z < 2) {
                const int i = (cidx & (HDIM - 1)) >> 1;
                float c0 = ct[s0 * 32 + i], sn0 = st[s0 * 32 + i];
                float c1 = ct[s1 * 32 + i], sn1 = st[s1 * 32 + i];
                float e = a0, o = a1;
                a0 = (e * c0 - o * sn0) * qscale;
                a1 = (e * sn0 + o * c0) * qscale;
                e = b0; o = b1;
                b0 = (e * c1 - o * sn1) * qscale;
                b1 = (e * sn1 + o * c1) * qscale;
            }
            store_split_pair(H, L, (size_t)r * N + cidx, a0, a1);
            store_split_pair(H, L, (size_t)(r + 8) * N + cidx, b0, b1);
        }
    }
}

// ---------------- plain GEMM (final O-proj) ----------------------------------
__global__ __launch_bounds__(256, 2) void gemm_mma(
    const __nv_bfloat16* __restrict__ Ah, const __nv_bfloat16* __restrict__ Al,
    const __nv_bfloat16* __restrict__ Bh, const __nv_bfloat16* __restrict__ Bl,
    float* __restrict__ C, int M, int N, int K)
{
    extern __shared__ char smem[];
    const uint32_t sb = smem_u32(smem);
    const int tid = threadIdx.x;
    const int lane = tid & 31;
    const int wid = tid >> 5;
    const int warp_m = wid >> 2;
    const int warp_n = wid & 3;
    const int m0 = blockIdx.y * 128, n0 = blockIdx.x * 128;

    float acc[4][4][4] = {};
    const __nv_bfloat16* srcs[4] = {Ah, Al, Bh, Bl};

    auto load_chunk = [&](int k0, int buf) {
        const uint32_t boff = sb + (uint32_t)buf * GBUF;
        #pragma unroll
        for (int p = 0; p < 4; ++p) {
            const __nv_bfloat16* src = srcs[p];
            const int r0 = (p < 2) ? m0 : n0;
            const uint32_t abase = boff + (uint32_t)p * GARR;
            #pragma unroll
            for (int t = 0; t < 2; ++t) {
                int u = tid + t * 256;
                int row = u >> 2, c = (u & 3) * 8;
                cp_async16(abase + (uint32_t)(row * GSTRIDE + c) * 2,
                           src + (size_t)(r0 + row) * K + k0 + c);
            }
        }
        asm volatile("cp.async.commit_group;" ::: "memory");
    };

    load_chunk(0, 0);

    const int nch = K / 32;
    for (int c = 0; c < nch; ++c) {
        asm volatile("cp.async.wait_group 0;" ::: "memory");
        __syncthreads();
        if (c + 1 < nch) load_chunk((c + 1) * 32, (c + 1) & 1);
        gemm_chunk_compute(sb + (uint32_t)(c & 1) * GBUF, lane, warp_m, warp_n, acc);
    }

    #pragma unroll
    for (int mi = 0; mi < 4; ++mi) {
        const int r = m0 + warp_m * 64 + mi * 16 + (lane >> 2);
        #pragma unroll
        for (int ni = 0; ni < 4; ++ni) {
            const int cidx = n0 + warp_n * 32 + ni * 8 + (lane & 3) * 2;
            float2 v0 = {acc[mi][ni][0], acc[mi][ni][1]};
            float2 v1 = {acc[mi][ni][2], acc[mi][ni][3]};
            *(float2*)(C + (size_t)r * N + cidx)       = v0;
            *(float2*)(C + (size_t)(r + 8) * N + cidx) = v1;
        }
    }
}

// ---------------- HMMA split-bf16 causal flash attention --------------------
// q-block 256, 8 warps x m32. Q in smem (hi/lo), KV 3-stage cp.async ring.
#define FSTR   72
#define FARR   (64 * FSTR * 2)          // 9216 B
#define FSTAGE (4 * FARR)               // 36864 B (Kh,Kl,Vh,Vl)
#define FQARR  (256 * FSTR * 2)         // 36864 B
#define FKVOFF (2 * FQARR)              // 73728
#define F_SMEM (FKVOFF + 3 * FSTAGE)    // 184320 B

__global__ __launch_bounds__(256, 1) void flash_mma(
    const __nv_bfloat16* __restrict__ Qh_, const __nv_bfloat16* __restrict__ Ql_,
    const __nv_bfloat16* __restrict__ Kh_, const __nv_bfloat16* __restrict__ Kl_,
    const __nv_bfloat16* __restrict__ Vh_, const __nv_bfloat16* __restrict__ Vl_,
    __nv_bfloat16* __restrict__ AOh, __nv_bfloat16* __restrict__ AOl)
{
    extern __shared__ char smem[];
    const uint32_t sb = smem_u32(smem);
    const int tid = threadIdx.x, lane = tid & 31, w = tid >> 5;
    const int b = blockIdx.z, h = blockIdx.y, q0 = blockIdx.x * 256;

    const size_t base_q = (size_t)(b * S_LEN + q0) * D_MODEL + h * HDIM;

    #pragma unroll
    for (int t = 0; t < 8; ++t) {
        int idx = tid + t * 256;
        int r = idx >> 3, c = (idx & 7) * 8;
        cp_async16(sb + (uint32_t)(r * FSTR + c) * 2, Qh_ + base_q + (size_t)r * D_MODEL + c);
        cp_async16(sb + FQARR + (uint32_t)(r * FSTR + c) * 2,
                   Ql_ + base_q + (size_t)r * D_MODEL + c);
    }
    asm volatile("cp.async.commit_group;" ::: "memory");

    const __nv_bfloat16* kv_src[4] = {Kh_, Kl_, Vh_, Vl_};
    auto load_kv = [&](int j, int st) {
        const size_t gb = (size_t)(b * S_LEN + j * 64) * D_MODEL + h * HDIM;
        const uint32_t sbase = sb + FKVOFF + (uint32_t)st * FSTAGE;
        #pragma unroll
        for (int p = 0; p < 4; ++p) {
            #pragma unroll
            for (int t = 0; t < 2; ++t) {
                int idx = tid + t * 256;
                int r = idx >> 3, c = (idx & 7) * 8;
                cp_async16(sbase + (uint32_t)p * FARR + (uint32_t)(r * FSTR + c) * 2,
                           kv_src[p] + gb + (size_t)r * D_MODEL + c);
            }
        }
        asm volatile("cp.async.commit_group;" ::: "memory");
    };

    const int jend = 4 * blockIdx.x + 4;
    load_kv(0, 0);
    if (jend > 1) load_kv(1, 1);

    float o[2][8][4] = {};
    float mrow[2][2] = {{-1e30f, -1e30f}, {-1e30f, -1e30f}};
    float lrow[2][2] = {};

    for (int j = 0; j < jend; ++j) {
        if (j + 1 < jend) {
            asm volatile("cp.async.wait_group 1;" ::: "memory");
        } else {
            asm volatile("cp.async.wait_group 0;" ::: "memory");
        }
        __syncthreads();
        if (j + 2 < jend) load_kv(j + 2, (j + 2) % 3);

        const int k0 = j * 64;
        if (k0 <= q0 + w * 32 + 31) {
            const uint32_t sbase = sb + FKVOFF + (uint32_t)(j % 3) * FSTAGE;

            float s[2][8][4] = {};
            #pragma unroll
            for (int ks = 0; ks < 4; ++ks) {
                uint32_t bh[8][2], bl[8][2];
                #pragma unroll
                for (int g = 0; g < 4; ++g) {
                    const int row = g * 16 + (lane >> 4) * 8 + (lane & 7);
                    const int col = ks * 16 + ((lane >> 3) & 1) * 8;
                    uint32_t addr = sbase + (uint32_t)(row * FSTR + col) * 2;
                    uint32_t r4[4];
                    ldmx4(r4, addr);
                    bh[2*g][0]=r4[0]; bh[2*g][1]=r4[1]; bh[2*g+1][0]=r4[2]; bh[2*g+1][1]=r4[3];
                    ldmx4(r4, addr + FARR);
                    bl[2*g][0]=r4[0]; bl[2*g][1]=r4[1]; bl[2*g+1][0]=r4[2]; bl[2*g+1][1]=r4[3];
                }
                #pragma unroll
                for (int mf = 0; mf < 2; ++mf) {
                    const int qrow = w * 32 + mf * 16 + (lane & 15);
                    const int qcol = ks * 16 + (lane >> 4) * 8;
                    uint32_t qaddr = sb + (uint32_t)(qrow * FSTR + qcol) * 2;
                    uint32_t qhf[4], qlf[4];
                    ldmx4(qhf, qaddr);
                    ldmx4(qlf, qaddr + FQARR);
                    #pragma unroll
                    for (int n = 0; n < 8; ++n) mma16816(s[mf][n], qhf, bh[n]);
                    #pragma unroll
                    for (int n = 0; n < 8; ++n) mma16816(s[mf][n], qhf, bl[n]);
                    #pragma unroll
                    for (int n = 0; n < 8; ++n) mma16816(s[mf][n], qlf, bh[n]);
                }
            }

            uint32_t ph[2][2][8];
            float a[2][2];
            #pragma unroll
            for (int mf = 0; mf < 2; ++mf) {
                const int gr = q0 + w * 32 + mf * 16 + (lane >> 2);
                if (k0 + 63 > q0 + w * 32 + mf * 16) {
                    #pragma unroll
                    for (int t = 0; t < 8; ++t) {
                        int c = k0 + t * 8 + 2 * (lane & 3);
                        if (c     > gr)     s[mf][t][0] = -1e30f;
                        if (c + 1 > gr)     s[mf][t][1] = -1e30f;
                        if (c     > gr + 8) s[mf][t][2] = -1e30f;
                        if (c + 1 > gr + 8) s[mf][t][3] = -1e30f;
                    }
                }
                float mx0 = -1e30f, mx1 = -1e30f;
                #pragma unroll
                for (int t = 0; t < 8; ++t) {
                    mx0 = fmaxf(mx0, fmaxf(s[mf][t][0], s[mf][t][1]));
                    mx1 = fmaxf(mx1, fmaxf(s[mf][t][2], s[mf][t][3]));
                }
                mx0 = fmaxf(mx0, __shfl_xor_sync(0xffffffffu, mx0, 1));
                mx0 = fmaxf(mx0, __shfl_xor_sync(0xffffffffu, mx0, 2));
                mx1 = fmaxf(mx1, __shfl_xor_sync(0xffffffffu, mx1, 1));
                mx1 = fmaxf(mx1, __shfl_xor_sync(0xffffffffu, mx1, 2));
                const float mn0 = fmaxf(mrow[mf][0], mx0), mn1 = fmaxf(mrow[mf][1], mx1);
                a[mf][0] = __expf(mrow[mf][0] - mn0);
                a[mf][1] = __expf(mrow[mf][1] - mn1);
                mrow[mf][0] = mn0; mrow[mf][1] = mn1;

                float ps0 = 0.0f, ps1 = 0.0f;
                #pragma unroll
                for (int t = 0; t < 8; ++t) {
                    float p0 = __expf(s[mf][t][0] - mn0), p1 = __expf(s[mf][t][1] - mn0);
                    float p2 = __expf(s[mf][t][2] - mn1), p3 = __expf(s[mf][t][3] - mn1);
                    ps0 += p0 + p1; ps1 += p2 + p3;
                    __nv_bfloat162 h01 = __float22bfloat162_rn(make_float2(p0, p1));
                    __nv_bfloat162 h23 = __float22bfloat162_rn(make_float2(p2, p3));
                    ph[mf][0][t] = *(uint32_t*)&h01;
                    ph[mf][1][t] = *(uint32_t*)&h23;
                }
                ps0 += __shfl_xor_sync(0xffffffffu, ps0, 1);
                ps0 += __shfl_xor_sync(0xffffffffu, ps0, 2);
                ps1 += __shfl_xor_sync(0xffffffffu, ps1, 1);
                ps1 += __shfl_xor_sync(0xffffffffu, ps1, 2);
                lrow[mf][0] = lrow[mf][0] * a[mf][0] + ps0;
                lrow[mf][1] = lrow[mf][1] * a[mf][1] + ps1;

                #pragma unroll
                for (int t = 0; t < 8; ++t) {
                    o[mf][t][0] *= a[mf][0]; o[mf][t][1] *= a[mf][0];
                    o[mf][t][2] *= a[mf][1]; o[mf][t][3] *= a[mf][1];
                }
            }

            #pragma unroll
            for (int ks = 0; ks < 4; ++ks) {
                uint32_t bvh[8][2], bvl[8][2];
                #pragma unroll
                for (int g = 0; g < 4; ++g) {
                    const int row = ks * 16 + (lane & 15);
                    const int col = g * 16 + (lane >> 4) * 8;
                    uint32_t addr = sbase + 2u * FARR + (uint32_t)(row * FSTR + col) * 2;
                    uint32_t r4[4];
                    ldmx4t(r4, addr);
                    bvh[2*g][0]=r4[0]; bvh[2*g][1]=r4[1]; bvh[2*g+1][0]=r4[2]; bvh[2*g+1][1]=r4[3];
                    ldmx4t(r4, addr + FARR);
                    bvl[2*g][0]=r4[0]; bvl[2*g][1]=r4[1]; bvl[2*g+1][0]=r4[2]; bvl[2*g+1][1]=r4[3];
                }
                #pragma unroll
                for (int mf = 0; mf < 2; ++mf) {
                    uint32_t pah[4] = {ph[mf][0][2*ks], ph[mf][1][2*ks],
                                       ph[mf][0][2*ks+1], ph[mf][1][2*ks+1]};
                    #pragma unroll
                    for (int n = 0; n < 8; ++n) mma16816(o[mf][n], pah, bvh[n]);
                    #pragma unroll
                    for (int n = 0; n < 8; ++n) mma16816(o[mf][n], pah, bvl[n]);
                }
            }
        }
    }

    const size_t ob = (size_t)b * S_LEN * D_MODEL + h * HDIM;
    #pragma unroll
    for (int mf = 0; mf < 2; ++mf) {
        const float inv0 = 1.0f / lrow[mf][0], inv1 = 1.0f / lrow[mf][1];
        const int gr = q0 + w * 32 + mf * 16 + (lane >> 2);
        #pragma unroll
        for (int t = 0; t < 8; ++t) {
            const int c = t * 8 + 2 * (lane & 3);
            store_split_pair(AOh, AOl, ob + (size_t)gr * D_MODEL + c,
                             o[mf][t][0] * inv0, o[mf][t][1] * inv0);
            store_split_pair(AOh, AOl, ob + (size_t)(gr + 8) * D_MODEL + c,
                             o[mf][t][2] * inv1, o[mf][t][3] * inv1);
        }
    }
}

// ---------------------------------------------------------------------------
extern "C" void kernel_launch(void* const* d_in, const int* in_sizes, int n_in,
                              void* d_out, int out_size)
{
    const float* x  = (const float*)d_in[0];
    const float* qw = (const float*)d_in[1];
    const float* kw = (const float*)d_in[2];
    const float* vw = (const float*)d_in[3];
    const float* ow = (const float*)d_in[4];

    const int M = in_sizes[0] / D_MODEL;
    const int B = M / S_LEN;
    const int W = D_MODEL * D_MODEL;

    void *pxh, *pxl, *pah, *pal, *pwh, *pwl;
    void *pqh, *pql, *pkh, *pkl, *pvh, *pvl, *pct, *pst;
    cudaGetSymbolAddress(&pxh, g_xh);  cudaGetSymbolAddress(&pxl, g_xl);
    cudaGetSymbolAddress(&pah, g_aoh); cudaGetSymbolAddress(&pal, g_aol);
    cudaGetSymbolAddress(&pwh, g_wh);  cudaGetSymbolAddress(&pwl, g_wl);
    cudaGetSymbolAddress(&pqh, g_qh);  cudaGetSymbolAddress(&pql, g_ql);
    cudaGetSymbolAddress(&pkh, g_kh);  cudaGetSymbolAddress(&pkl, g_kl);
    cudaGetSymbolAddress(&pvh, g_vh);  cudaGetSymbolAddress(&pvl, g_vl);
    cudaGetSymbolAddress(&pct, g_ct);  cudaGetSymbolAddress(&pst, g_st);
    __nv_bfloat16* xh = (__nv_bfloat16*)pxh;  __nv_bfloat16* xl = (__nv_bfloat16*)pxl;
    __nv_bfloat16* aoh = (__nv_bfloat16*)pah; __nv_bfloat16* aol = (__nv_bfloat16*)pal;
    __nv_bfloat16* wh = (__nv_bfloat16*)pwh;  __nv_bfloat16* wl = (__nv_bfloat16*)pwl;
    __nv_bfloat16* qhp = (__nv_bfloat16*)pqh; __nv_bfloat16* qlp = (__nv_bfloat16*)pql;
    __nv_bfloat16* khp = (__nv_bfloat16*)pkh; __nv_bfloat16* klp = (__nv_bfloat16*)pkl;
    __nv_bfloat16* vhp = (__nv_bfloat16*)pvh; __nv_bfloat16* vlp = (__nv_bfloat16*)pvl;
    float* ct = (float*)pct; float* st = (float*)pst;

    int n4x = M * D_MODEL / 4;
    split_kernel<<<(n4x + 255) / 256, 256>>>(x, xh, xl, n4x);
    int n4w = W / 4;
    dim3 wgrid((n4w + 255) / 256, 4);
    split_w4<<<wgrid, 256>>>(qw, kw, vw, ow, wh, wl, n4w);
    rope_tab<<<(S_LEN * 32 + 255) / 256, 256>>>(ct, st);

    cudaFuncSetAttribute(gemm_qkv, cudaFuncAttributeMaxDynamicSharedMemorySize, G_SMEM_SZ);
    dim3 qkvgrid(D_MODEL / 128, M / 128, 3);
    gemm_qkv<<<qkvgrid, 256, G_SMEM_SZ>>>(xh, xl, wh, wl,
                                          qhp, qlp, khp, klp, vhp, vlp,
                                          ct, st, M, D_MODEL, D_MODEL);

    cudaFuncSetAttribute(flash_mma, cudaFuncAttributeMaxDynamicSharedMemorySize, F_SMEM);
    dim3 fgrid(S_LEN / 256, NHEAD, B);
    flash_mma<<<fgrid, 256, F_SMEM>>>(qhp, qlp, khp, klp, vhp, vlp, aoh, aol);

    cudaFuncSetAttribute(gemm_mma, cudaFuncAttributeMaxDynamicSharedMemorySize, G_SMEM_SZ);
    dim3 ggrid(D_MODEL / 128, M / 128);
    gemm_mma<<<ggrid, 256, G_SMEM_SZ>>>(aoh, aol, wh + 3 * W, wl + 3 * W,
                                        (float*)d_out, M, D_MODEL, D_MODEL);
}

// round 13
// speedup vs baseline: 1.0858x; 1.0312x over previous
#include <cuda_runtime.h>
#include <cuda_bf16.h>
#include <math.h>
#include <stdint.h>

#define D_MODEL 1024
#define S_LEN   2048
#define NHEAD   16
#define HDIM    64
#define MAXB    4
#define MMAX    (MAXB * S_LEN)

// ---------------- scratch (__device__ globals; no allocs allowed) ----------
__device__ __nv_bfloat16 g_xh [MMAX * D_MODEL];
__device__ __nv_bfloat16 g_xl [MMAX * D_MODEL];
__device__ __nv_bfloat16 g_aoh[MMAX * D_MODEL];
__device__ __nv_bfloat16 g_aol[MMAX * D_MODEL];
__device__ __nv_bfloat16 g_wh [4 * D_MODEL * D_MODEL];
__device__ __nv_bfloat16 g_wl [4 * D_MODEL * D_MODEL];
__device__ __nv_bfloat16 g_qh [MMAX * D_MODEL];
__device__ __nv_bfloat16 g_ql [MMAX * D_MODEL];
__device__ __nv_bfloat16 g_kh [MMAX * D_MODEL];
__device__ __nv_bfloat16 g_kl [MMAX * D_MODEL];
__device__ __nv_bfloat16 g_vh [MMAX * D_MODEL];
__device__ __nv_bfloat16 g_vl [MMAX * D_MODEL];
__device__ float g_ct[S_LEN * 32];
__device__ float g_st[S_LEN * 32];

// ---------------- helpers ----------------------------------------------------
__device__ __forceinline__ uint32_t smem_u32(const void* p) {
    uint32_t a;
    asm("{ .reg .u64 t; cvta.to.shared.u64 t, %1; cvt.u32.u64 %0, t; }" : "=r"(a) : "l"(p));
    return a;
}
__device__ __forceinline__ void cp_async16(uint32_t saddr, const void* gptr) {
    asm volatile("cp.async.cg.shared.global [%0], [%1], 16;" :: "r"(saddr), "l"(gptr));
}
__device__ __forceinline__ void ldmx4(uint32_t* r, uint32_t addr) {
    asm volatile("ldmatrix.sync.aligned.m8n8.x4.shared.b16 {%0,%1,%2,%3}, [%4];"
                 : "=r"(r[0]), "=r"(r[1]), "=r"(r[2]), "=r"(r[3]) : "r"(addr));
}
__device__ __forceinline__ void ldmx4t(uint32_t* r, uint32_t addr) {
    asm volatile("ldmatrix.sync.aligned.m8n8.x4.trans.shared.b16 {%0,%1,%2,%3}, [%4];"
                 : "=r"(r[0]), "=r"(r[1]), "=r"(r[2]), "=r"(r[3]) : "r"(addr));
}
__device__ __forceinline__ void mma16816(float* d, const uint32_t* a, const uint32_t* b) {
    asm volatile("mma.sync.aligned.m16n8k16.row.col.f32.bf16.bf16.f32 "
                 "{%0,%1,%2,%3}, {%4,%5,%6,%7}, {%8,%9}, {%0,%1,%2,%3};"
                 : "+f"(d[0]), "+f"(d[1]), "+f"(d[2]), "+f"(d[3])
                 : "r"(a[0]), "r"(a[1]), "r"(a[2]), "r"(a[3]), "r"(b[0]), "r"(b[1]));
}
__device__ __forceinline__ void store_split_pair(
    __nv_bfloat16* H, __nv_bfloat16* L, size_t off, float a, float b)
{
    __nv_bfloat162 hi = __float22bfloat162_rn(make_float2(a, b));
    __nv_bfloat162 lo = __float22bfloat162_rn(
        make_float2(a - __bfloat162float(hi.x), b - __bfloat162float(hi.y)));
    *(__nv_bfloat162*)(H + off) = hi;
    *(__nv_bfloat162*)(L + off) = lo;
}

// ---------------- split fp32 -> bf16 hi/lo ----------------------------------
__global__ void split_kernel(const float* __restrict__ X,
                             __nv_bfloat16* __restrict__ H,
                             __nv_bfloat16* __restrict__ L, int n4)
{
    int i = blockIdx.x * blockDim.x + threadIdx.x;
    if (i >= n4) return;
    float4 v = ((const float4*)X)[i];
    __nv_bfloat16 h0 = __float2bfloat16(v.x), h1 = __float2bfloat16(v.y);
    __nv_bfloat16 h2 = __float2bfloat16(v.z), h3 = __float2bfloat16(v.w);
    __nv_bfloat16 l0 = __float2bfloat16(v.x - __bfloat162float(h0));
    __nv_bfloat16 l1 = __float2bfloat16(v.y - __bfloat162float(h1));
    __nv_bfloat16 l2 = __float2bfloat16(v.z - __bfloat162float(h2));
    __nv_bfloat16 l3 = __float2bfloat16(v.w - __bfloat162float(h3));
    __nv_bfloat162 hA = {h0, h1}, hB = {h2, h3}, lA = {l0, l1}, lB = {l2, l3};
    uint2 hv, lv;
    hv.x = *(uint32_t*)&hA; hv.y = *(uint32_t*)&hB;
    lv.x = *(uint32_t*)&lA; lv.y = *(uint32_t*)&lB;
    ((uint2*)H)[i] = hv;
    ((uint2*)L)[i] = lv;
}

__global__ void split_w4(const float* __restrict__ W0, const float* __restrict__ W1,
                         const float* __restrict__ W2, const float* __restrict__ W3,
                         __nv_bfloat16* __restrict__ H, __nv_bfloat16* __restrict__ L,
                         int n4)
{
    int i = blockIdx.x * blockDim.x + threadIdx.x;
    if (i >= n4) return;
    int z = blockIdx.y;
    const float* X = (z == 0) ? W0 : (z == 1) ? W1 : (z == 2) ? W2 : W3;
    float4 v = ((const float4*)X)[i];
    __nv_bfloat16 h0 = __float2bfloat16(v.x), h1 = __float2bfloat16(v.y);
    __nv_bfloat16 h2 = __float2bfloat16(v.z), h3 = __float2bfloat16(v.w);
    __nv_bfloat16 l0 = __float2bfloat16(v.x - __bfloat162float(h0));
    __nv_bfloat16 l1 = __float2bfloat16(v.y - __bfloat162float(h1));
    __nv_bfloat16 l2 = __float2bfloat16(v.z - __bfloat162float(h2));
    __nv_bfloat16 l3 = __float2bfloat16(v.w - __bfloat162float(h3));
    __nv_bfloat162 hA = {h0, h1}, hB = {h2, h3}, lA = {l0, l1}, lB = {l2, l3};
    uint2 hv, lv;
    hv.x = *(uint32_t*)&hA; hv.y = *(uint32_t*)&hB;
    lv.x = *(uint32_t*)&lA; lv.y = *(uint32_t*)&lB;
    ((uint2*)(H + (size_t)z * D_MODEL * D_MODEL))[i] = hv;
    ((uint2*)(L + (size_t)z * D_MODEL * D_MODEL))[i] = lv;
}

// ---------------- RoPE cos/sin table ----------------------------------------
__global__ void rope_tab(float* __restrict__ ct, float* __restrict__ st)
{
    int idx = blockIdx.x * blockDim.x + threadIdx.x;
    if (idx >= S_LEN * 32) return;
    int s = idx >> 5, i = idx & 31;
    float inv = expf(-logf(10000.0f) * ((float)i / 32.0f));
    float sn, cs;
    sincosf((float)s * inv, &sn, &cs);
    ct[idx] = cs; st[idx] = sn;
}

// ---------------- GEMM core: 128x128, 2-stage ring, ONE sync per chunk ------
#define GSTRIDE 40
#define GARR    (128 * GSTRIDE * 2)      // 10240 B
#define GBUF    (4 * GARR)               // 40960 B per stage
#define G_SMEM_SZ (2 * GBUF)             // 81920 B -> 2 CTAs/SM

__device__ __forceinline__ void gemm_chunk_compute(
    uint32_t boff, int lane, int warp_m, int warp_n, float acc[4][4][4])
{
    const int arow = warp_m * 64 + (lane & 15);
    const int brow_base = warp_n * 32 + ((lane >> 4) * 8) + (lane & 7);
    #pragma unroll
    for (int ks = 0; ks < 2; ++ks) {
        const int acol = ks * 16 + (lane >> 4) * 8;
        const int bcol = ks * 16 + ((lane >> 3) & 1) * 8;
        uint32_t bh[4][2], bl[4][2];
        #pragma unroll
        for (int g = 0; g < 2; ++g) {
            uint32_t addr = boff + 2 * GARR +
                            (uint32_t)((brow_base + g * 16) * GSTRIDE + bcol) * 2;
            uint32_t r[4];
            ldmx4(r, addr);
            bh[2*g][0] = r[0]; bh[2*g][1] = r[1];
            bh[2*g+1][0] = r[2]; bh[2*g+1][1] = r[3];
            ldmx4(r, addr + GARR);
            bl[2*g][0] = r[0]; bl[2*g][1] = r[1];
            bl[2*g+1][0] = r[2]; bl[2*g+1][1] = r[3];
        }
        #pragma unroll
        for (int half = 0; half < 2; ++half) {
            uint32_t ah[2][4], al[2][4];
            #pragma unroll
            for (int mi = 0; mi < 2; ++mi) {
                uint32_t addr = boff +
                    (uint32_t)((arow + (half * 2 + mi) * 16) * GSTRIDE + acol) * 2;
                ldmx4(ah[mi], addr);
                ldmx4(al[mi], addr + GARR);
            }
            #pragma unroll
            for (int mi = 0; mi < 2; ++mi)
                #pragma unroll
                for (int ni = 0; ni < 4; ++ni) {
                    float* a = acc[half * 2 + mi][ni];
                    mma16816(a, ah[mi], bh[ni]);
                    mma16816(a, ah[mi], bl[ni]);
                    mma16816(a, al[mi], bh[ni]);
                }
        }
    }
}

// ---------------- fused QKV mega-GEMM ----------------------------------------
__global__ __launch_bounds__(256, 2) void gemm_qkv(
    const __nv_bfloat16* __restrict__ Ah, const __nv_bfloat16* __restrict__ Al,
    const __nv_bfloat16* __restrict__ Wh, const __nv_bfloat16* __restrict__ Wl,
    __nv_bfloat16* __restrict__ Qh, __nv_bfloat16* __restrict__ Ql,
    __nv_bfloat16* __restrict__ Kh, __nv_bfloat16* __restrict__ Kl,
    __nv_bfloat16* __restrict__ Vh, __nv_bfloat16* __restrict__ Vl,
    const float* __restrict__ ct, const float* __restrict__ st,
    int M, int N, int K)
{
    extern __shared__ char smem[];
    const uint32_t sb = smem_u32(smem);
    const int tid = threadIdx.x;
    const int lane = tid & 31;
    const int wid = tid >> 5;
    const int warp_m = wid >> 2;
    const int warp_n = wid & 3;
    const int m0 = blockIdx.y * 128, n0 = blockIdx.x * 128;
    const int z = blockIdx.z;

    const __nv_bfloat16* Bh = Wh + (size_t)z * K * N;
    const __nv_bfloat16* Bl = Wl + (size_t)z * K * N;

    float acc[4][4][4] = {};
    const __nv_bfloat16* srcs[4] = {Ah, Al, Bh, Bl};

    auto load_chunk = [&](int k0, int buf) {
        const uint32_t boff = sb + (uint32_t)buf * GBUF;
        #pragma unroll
        for (int p = 0; p < 4; ++p) {
            const __nv_bfloat16* src = srcs[p];
            const int r0 = (p < 2) ? m0 : n0;
            const uint32_t abase = boff + (uint32_t)p * GARR;
            #pragma unroll
            for (int t = 0; t < 2; ++t) {
                int u = tid + t * 256;
                int row = u >> 2, c = (u & 3) * 8;
                cp_async16(abase + (uint32_t)(row * GSTRIDE + c) * 2,
                           src + (size_t)(r0 + row) * K + k0 + c);
            }
        }
        asm volatile("cp.async.commit_group;" ::: "memory");
    };

    load_chunk(0, 0);

    const int nch = K / 32;
    for (int c = 0; c < nch; ++c) {
        asm volatile("cp.async.wait_group 0;" ::: "memory");
        __syncthreads();
        if (c + 1 < nch) load_chunk((c + 1) * 32, (c + 1) & 1);
        gemm_chunk_compute(sb + (uint32_t)(c & 1) * GBUF, lane, warp_m, warp_n, acc);
    }

    __nv_bfloat16* H = (z == 0) ? Qh : (z == 1) ? Kh : Vh;
    __nv_bfloat16* L = (z == 0) ? Ql : (z == 1) ? Kl : Vl;
    const float qscale = (z == 0) ? 0.125f : 1.0f;

    #pragma unroll
    for (int mi = 0; mi < 4; ++mi) {
        const int r = m0 + warp_m * 64 + mi * 16 + (lane >> 2);
        const int s0 = r & (S_LEN - 1);
        const int s1 = (r + 8) & (S_LEN - 1);
        #pragma unroll
        for (int ni = 0; ni < 4; ++ni) {
            const int cidx = n0 + warp_n * 32 + ni * 8 + (lane & 3) * 2;
            float a0 = acc[mi][ni][0], a1 = acc[mi][ni][1];
            float b0 = acc[mi][ni][2], b1 = acc[mi][ni][3];
            if (z < 2) {
                const int i = (cidx & (HDIM - 1)) >> 1;
                float c0 = ct[s0 * 32 + i], sn0 = st[s0 * 32 + i];
                float c1 = ct[s1 * 32 + i], sn1 = st[s1 * 32 + i];
                float e = a0, o = a1;
                a0 = (e * c0 - o * sn0) * qscale;
                a1 = (e * sn0 + o * c0) * qscale;
                e = b0; o = b1;
                b0 = (e * c1 - o * sn1) * qscale;
                b1 = (e * sn1 + o * c1) * qscale;
            }
            store_split_pair(H, L, (size_t)r * N + cidx, a0, a1);
            store_split_pair(H, L, (size_t)(r + 8) * N + cidx, b0, b1);
        }
    }
}

// ---------------- plain GEMM (final O-proj) ----------------------------------
__global__ __launch_bounds__(256, 2) void gemm_mma(
    const __nv_bfloat16* __restrict__ Ah, const __nv_bfloat16* __restrict__ Al,
    const __nv_bfloat16* __restrict__ Bh, const __nv_bfloat16* __restrict__ Bl,
    float* __restrict__ C, int M, int N, int K)
{
    extern __shared__ char smem[];
    const uint32_t sb = smem_u32(smem);
    const int tid = threadIdx.x;
    const int lane = tid & 31;
    const int wid = tid >> 5;
    const int warp_m = wid >> 2;
    const int warp_n = wid & 3;
    const int m0 = blockIdx.y * 128, n0 = blockIdx.x * 128;

    float acc[4][4][4] = {};
    const __nv_bfloat16* srcs[4] = {Ah, Al, Bh, Bl};

    auto load_chunk = [&](int k0, int buf) {
        const uint32_t boff = sb + (uint32_t)buf * GBUF;
        #pragma unroll
        for (int p = 0; p < 4; ++p) {
            const __nv_bfloat16* src = srcs[p];
            const int r0 = (p < 2) ? m0 : n0;
            const uint32_t abase = boff + (uint32_t)p * GARR;
            #pragma unroll
            for (int t = 0; t < 2; ++t) {
                int u = tid + t * 256;
                int row = u >> 2, c = (u & 3) * 8;
                cp_async16(abase + (uint32_t)(row * GSTRIDE + c) * 2,
                           src + (size_t)(r0 + row) * K + k0 + c);
            }
        }
        asm volatile("cp.async.commit_group;" ::: "memory");
    };

    load_chunk(0, 0);

    const int nch = K / 32;
    for (int c = 0; c < nch; ++c) {
        asm volatile("cp.async.wait_group 0;" ::: "memory");
        __syncthreads();
        if (c + 1 < nch) load_chunk((c + 1) * 32, (c + 1) & 1);
        gemm_chunk_compute(sb + (uint32_t)(c & 1) * GBUF, lane, warp_m, warp_n, acc);
    }

    #pragma unroll
    for (int mi = 0; mi < 4; ++mi) {
        const int r = m0 + warp_m * 64 + mi * 16 + (lane >> 2);
        #pragma unroll
        for (int ni = 0; ni < 4; ++ni) {
            const int cidx = n0 + warp_n * 32 + ni * 8 + (lane & 3) * 2;
            float2 v0 = {acc[mi][ni][0], acc[mi][ni][1]};
            float2 v1 = {acc[mi][ni][2], acc[mi][ni][3]};
            *(float2*)(C + (size_t)r * N + cidx)       = v0;
            *(float2*)(C + (size_t)(r + 8) * N + cidx) = v1;
        }
    }
}

// ---------------- persistent, statically-balanced causal flash --------------
// q-block 256 rows. CTA p processes 4 tiles whose causal costs sum to a
// uniform 18 units: {p, 4NB-1-p, 4NB+p, 8NB-1-p}, NB = NHEAD*B.
#define FSTR   72
#define FARR   (64 * FSTR * 2)          // 9216 B
#define FSTAGE (4 * FARR)               // 36864 B (Kh,Kl,Vh,Vl)
#define FQARR  (256 * FSTR * 2)         // 36864 B
#define FKVOFF (2 * FQARR)              // 73728
#define F_SMEM (FKVOFF + 3 * FSTAGE)    // 184320 B

__global__ __launch_bounds__(256, 1) void flash_mma(
    const __nv_bfloat16* __restrict__ Qh_, const __nv_bfloat16* __restrict__ Ql_,
    const __nv_bfloat16* __restrict__ Kh_, const __nv_bfloat16* __restrict__ Kl_,
    const __nv_bfloat16* __restrict__ Vh_, const __nv_bfloat16* __restrict__ Vl_,
    __nv_bfloat16* __restrict__ AOh, __nv_bfloat16* __restrict__ AOl, int NB)
{
    extern __shared__ char smem[];
    const uint32_t sb = smem_u32(smem);
    const int tid = threadIdx.x, lane = tid & 31, w = tid >> 5;
    const int p = blockIdx.x;

    const __nv_bfloat16* kv_src[4] = {Kh_, Kl_, Vh_, Vl_};

    #pragma unroll 1
    for (int pass = 0; pass < 4; ++pass) {
        int s;
        switch (pass) {
            case 0:  s = p;              break;
            case 1:  s = 4 * NB - 1 - p; break;
            case 2:  s = 4 * NB + p;     break;
            default: s = 8 * NB - 1 - p; break;
        }
        const int bx = s / NB;
        const int r_ = s % NB;
        const int h = r_ & (NHEAD - 1);
        const int b = r_ >> 4;                    // NHEAD == 16
        const int q0 = bx * 256;

        __syncthreads();   // all warps done reading smem of previous tile

        const size_t base_q = (size_t)(b * S_LEN + q0) * D_MODEL + h * HDIM;
        #pragma unroll
        for (int t = 0; t < 8; ++t) {
            int idx = tid + t * 256;
            int r = idx >> 3, c = (idx & 7) * 8;
            cp_async16(sb + (uint32_t)(r * FSTR + c) * 2,
                       Qh_ + base_q + (size_t)r * D_MODEL + c);
            cp_async16(sb + FQARR + (uint32_t)(r * FSTR + c) * 2,
                       Ql_ + base_q + (size_t)r * D_MODEL + c);
        }
        asm volatile("cp.async.commit_group;" ::: "memory");

        auto load_kv = [&](int j, int st) {
            const size_t gb = (size_t)(b * S_LEN + j * 64) * D_MODEL + h * HDIM;
            const uint32_t sbase = sb + FKVOFF + (uint32_t)st * FSTAGE;
            #pragma unroll
            for (int pp = 0; pp < 4; ++pp) {
                #pragma unroll
                for (int t = 0; t < 2; ++t) {
                    int idx = tid + t * 256;
                    int r = idx >> 3, c = (idx & 7) * 8;
                    cp_async16(sbase + (uint32_t)pp * FARR + (uint32_t)(r * FSTR + c) * 2,
                               kv_src[pp] + gb + (size_t)r * D_MODEL + c);
                }
            }
            asm volatile("cp.async.commit_group;" ::: "memory");
        };

        const int jend = 4 * bx + 4;
        load_kv(0, 0);
        if (jend > 1) load_kv(1, 1);

        float o[2][8][4] = {};
        float mrow[2][2] = {{-1e30f, -1e30f}, {-1e30f, -1e30f}};
        float lrow[2][2] = {};

        for (int j = 0; j < jend; ++j) {
            if (j + 1 < jend) {
                asm volatile("cp.async.wait_group 1;" ::: "memory");
            } else {
                asm volatile("cp.async.wait_group 0;" ::: "memory");
            }
            __syncthreads();
            if (j + 2 < jend) load_kv(j + 2, (j + 2) % 3);

            const int k0 = j * 64;
            if (k0 <= q0 + w * 32 + 31) {
                const uint32_t sbase = sb + FKVOFF + (uint32_t)(j % 3) * FSTAGE;

                float sreg[2][8][4] = {};
                #pragma unroll
                for (int ks = 0; ks < 4; ++ks) {
                    uint32_t bh[8][2], bl[8][2];
                    #pragma unroll
                    for (int g = 0; g < 4; ++g) {
                        const int row = g * 16 + (lane >> 4) * 8 + (lane & 7);
                        const int col = ks * 16 + ((lane >> 3) & 1) * 8;
                        uint32_t addr = sbase + (uint32_t)(row * FSTR + col) * 2;
                        uint32_t r4[4];
                        ldmx4(r4, addr);
                        bh[2*g][0]=r4[0]; bh[2*g][1]=r4[1]; bh[2*g+1][0]=r4[2]; bh[2*g+1][1]=r4[3];
                        ldmx4(r4, addr + FARR);
                        bl[2*g][0]=r4[0]; bl[2*g][1]=r4[1]; bl[2*g+1][0]=r4[2]; bl[2*g+1][1]=r4[3];
                    }
                    #pragma unroll
                    for (int mf = 0; mf < 2; ++mf) {
                        const int qrow = w * 32 + mf * 16 + (lane & 15);
                        const int qcol = ks * 16 + (lane >> 4) * 8;
                        uint32_t qaddr = sb + (uint32_t)(qrow * FSTR + qcol) * 2;
                        uint32_t qhf[4], qlf[4];
                        ldmx4(qhf, qaddr);
                        ldmx4(qlf, qaddr + FQARR);
                        #pragma unroll
                        for (int n = 0; n < 8; ++n) mma16816(sreg[mf][n], qhf, bh[n]);
                        #pragma unroll
                        for (int n = 0; n < 8; ++n) mma16816(sreg[mf][n], qhf, bl[n]);
                        #pragma unroll
                        for (int n = 0; n < 8; ++n) mma16816(sreg[mf][n], qlf, bh[n]);
                    }
                }

                uint32_t ph[2][2][8];
                float a[2][2];
                #pragma unroll
                for (int mf = 0; mf < 2; ++mf) {
                    const int gr = q0 + w * 32 + mf * 16 + (lane >> 2);
                    if (k0 + 63 > q0 + w * 32 + mf * 16) {
                        #pragma unroll
                        for (int t = 0; t < 8; ++t) {
                            int c = k0 + t * 8 + 2 * (lane & 3);
                            if (c     > gr)     sreg[mf][t][0] = -1e30f;
                            if (c + 1 > gr)     sreg[mf][t][1] = -1e30f;
                            if (c     > gr + 8) sreg[mf][t][2] = -1e30f;
                            if (c + 1 > gr + 8) sreg[mf][t][3] = -1e30f;
                        }
                    }
                    float mx0 = -1e30f, mx1 = -1e30f;
                    #pragma unroll
                    for (int t = 0; t < 8; ++t) {
                        mx0 = fmaxf(mx0, fmaxf(sreg[mf][t][0], sreg[mf][t][1]));
                        mx1 = fmaxf(mx1, fmaxf(sreg[mf][t][2], sreg[mf][t][3]));
                    }
                    mx0 = fmaxf(mx0, __shfl_xor_sync(0xffffffffu, mx0, 1));
                    mx0 = fmaxf(mx0, __shfl_xor_sync(0xffffffffu, mx0, 2));
                    mx1 = fmaxf(mx1, __shfl_xor_sync(0xffffffffu, mx1, 1));
                    mx1 = fmaxf(mx1, __shfl_xor_sync(0xffffffffu, mx1, 2));
                    const float mn0 = fmaxf(mrow[mf][0], mx0), mn1 = fmaxf(mrow[mf][1], mx1);
                    a[mf][0] = __expf(mrow[mf][0] - mn0);
                    a[mf][1] = __expf(mrow[mf][1] - mn1);
                    mrow[mf][0] = mn0; mrow[mf][1] = mn1;

                    float ps0 = 0.0f, ps1 = 0.0f;
                    #pragma unroll
                    for (int t = 0; t < 8; ++t) {
                        float p0 = __expf(sreg[mf][t][0] - mn0), p1 = __expf(sreg[mf][t][1] - mn0);
                        float p2 = __expf(sreg[mf][t][2] - mn1), p3 = __expf(sreg[mf][t][3] - mn1);
                        ps0 += p0 + p1; ps1 += p2 + p3;
                        __nv_bfloat162 h01 = __float22bfloat162_rn(make_float2(p0, p1));
                        __nv_bfloat162 h23 = __float22bfloat162_rn(make_float2(p2, p3));
                        ph[mf][0][t] = *(uint32_t*)&h01;
                        ph[mf][1][t] = *(uint32_t*)&h23;
                    }
                    ps0 += __shfl_xor_sync(0xffffffffu, ps0, 1);
                    ps0 += __shfl_xor_sync(0xffffffffu, ps0, 2);
                    ps1 += __shfl_xor_sync(0xffffffffu, ps1, 1);
                    ps1 += __shfl_xor_sync(0xffffffffu, ps1, 2);
                    lrow[mf][0] = lrow[mf][0] * a[mf][0] + ps0;
                    lrow[mf][1] = lrow[mf][1] * a[mf][1] + ps1;

                    #pragma unroll
                    for (int t = 0; t < 8; ++t) {
                        o[mf][t][0] *= a[mf][0]; o[mf][t][1] *= a[mf][0];
                        o[mf][t][2] *= a[mf][1]; o[mf][t][3] *= a[mf][1];
                    }
                }

                #pragma unroll
                for (int ks = 0; ks < 4; ++ks) {
                    uint32_t bvh[8][2], bvl[8][2];
                    #pragma unroll
                    for (int g = 0; g < 4; ++g) {
                        const int row = ks * 16 + (lane & 15);
                        const int col = g * 16 + (lane >> 4) * 8;
                        uint32_t addr = sbase + 2u * FARR + (uint32_t)(row * FSTR + col) * 2;
                        uint32_t r4[4];
                        ldmx4t(r4, addr);
                        bvh[2*g][0]=r4[0]; bvh[2*g][1]=r4[1]; bvh[2*g+1][0]=r4[2]; bvh[2*g+1][1]=r4[3];
                        ldmx4t(r4, addr + FARR);
                        bvl[2*g][0]=r4[0]; bvl[2*g][1]=r4[1]; bvl[2*g+1][0]=r4[2]; bvl[2*g+1][1]=r4[3];
                    }
                    #pragma unroll
                    for (int mf = 0; mf < 2; ++mf) {
                        uint32_t pah[4] = {ph[mf][0][2*ks], ph[mf][1][2*ks],
                                           ph[mf][0][2*ks+1], ph[mf][1][2*ks+1]};
                        #pragma unroll
                        for (int n = 0; n < 8; ++n) mma16816(o[mf][n], pah, bvh[n]);
                        #pragma unroll
                        for (int n = 0; n < 8; ++n) mma16816(o[mf][n], pah, bvl[n]);
                    }
                }
            }
        }

        const size_t ob = (size_t)b * S_LEN * D_MODEL + h * HDIM;
        #pragma unroll
        for (int mf = 0; mf < 2; ++mf) {
            const float inv0 = 1.0f / lrow[mf][0], inv1 = 1.0f / lrow[mf][1];
            const int gr = q0 + w * 32 + mf * 16 + (lane >> 2);
            #pragma unroll
            for (int t = 0; t < 8; ++t) {
                const int c = t * 8 + 2 * (lane & 3);
                store_split_pair(AOh, AOl, ob + (size_t)gr * D_MODEL + c,
                                 o[mf][t][0] * inv0, o[mf][t][1] * inv0);
                store_split_pair(AOh, AOl, ob + (size_t)(gr + 8) * D_MODEL + c,
                                 o[mf][t][2] * inv1, o[mf][t][3] * inv1);
            }
        }
    }
}

// ---------------------------------------------------------------------------
extern "C" void kernel_launch(void* const* d_in, const int* in_sizes, int n_in,
                              void* d_out, int out_size)
{
    const float* x  = (const float*)d_in[0];
    const float* qw = (const float*)d_in[1];
    const float* kw = (const float*)d_in[2];
    const float* vw = (const float*)d_in[3];
    const float* ow = (const float*)d_in[4];

    const int M = in_sizes[0] / D_MODEL;
    const int B = M / S_LEN;
    const int W = D_MODEL * D_MODEL;

    void *pxh, *pxl, *pah, *pal, *pwh, *pwl;
    void *pqh, *pql, *pkh, *pkl, *pvh, *pvl, *pct, *pst;
    cudaGetSymbolAddress(&pxh, g_xh);  cudaGetSymbolAddress(&pxl, g_xl);
    cudaGetSymbolAddress(&pah, g_aoh); cudaGetSymbolAddress(&pal, g_aol);
    cudaGetSymbolAddress(&pwh, g_wh);  cudaGetSymbolAddress(&pwl, g_wl);
    cudaGetSymbolAddress(&pqh, g_qh);  cudaGetSymbolAddress(&pql, g_ql);
    cudaGetSymbolAddress(&pkh, g_kh);  cudaGetSymbolAddress(&pkl, g_kl);
    cudaGetSymbolAddress(&pvh, g_vh);  cudaGetSymbolAddress(&pvl, g_vl);
    cudaGetSymbolAddress(&pct, g_ct);  cudaGetSymbolAddress(&pst, g_st);
    __nv_bfloat16* xh = (__nv_bfloat16*)pxh;  __nv_bfloat16* xl = (__nv_bfloat16*)pxl;
    __nv_bfloat16* aoh = (__nv_bfloat16*)pah; __nv_bfloat16* aol = (__nv_bfloat16*)pal;
    __nv_bfloat16* wh = (__nv_bfloat16*)pwh;  __nv_bfloat16* wl = (__nv_bfloat16*)pwl;
    __nv_bfloat16* qhp = (__nv_bfloat16*)pqh; __nv_bfloat16* qlp = (__nv_bfloat16*)pql;
    __nv_bfloat16* khp = (__nv_bfloat16*)pkh; __nv_bfloat16* klp = (__nv_bfloat16*)pkl;
    __nv_bfloat16* vhp = (__nv_bfloat16*)pvh; __nv_bfloat16* vlp = (__nv_bfloat16*)pvl;
    float* ct = (float*)pct; float* st = (float*)pst;

    int n4x = M * D_MODEL / 4;
    split_kernel<<<(n4x + 255) / 256, 256>>>(x, xh, xl, n4x);
    int n4w = W / 4;
    dim3 wgrid((n4w + 255) / 256, 4);
    split_w4<<<wgrid, 256>>>(qw, kw, vw, ow, wh, wl, n4w);
    rope_tab<<<(S_LEN * 32 + 255) / 256, 256>>>(ct, st);

    cudaFuncSetAttribute(gemm_qkv, cudaFuncAttributeMaxDynamicSharedMemorySize, G_SMEM_SZ);
    dim3 qkvgrid(D_MODEL / 128, M / 128, 3);
    gemm_qkv<<<qkvgrid, 256, G_SMEM_SZ>>>(xh, xl, wh, wl,
                                          qhp, qlp, khp, klp, vhp, vlp,
                                          ct, st, M, D_MODEL, D_MODEL);

    cudaFuncSetAttribute(flash_mma, cudaFuncAttributeMaxDynamicSharedMemorySize, F_SMEM);
    const int NB = NHEAD * B;               // 64 for B=4
    flash_mma<<<2 * NB, 256, F_SMEM>>>(qhp, qlp, khp, klp, vhp, vlp, aoh, aol, NB);

    cudaFuncSetAttribute(gemm_mma, cudaFuncAttributeMaxDynamicSharedMemorySize, G_SMEM_SZ);
    dim3 ggrid(D_MODEL / 128, M / 128);
    gemm_mma<<<ggrid, 256, G_SMEM_SZ>>>(aoh, aol, wh + 3 * W, wl + 3 * W,
                                        (float*)d_out, M, D_MODEL, D_MODEL);
}

// round 14
// speedup vs baseline: 1.1339x; 1.0443x over previous
#include <cuda_runtime.h>
#include <cuda_fp16.h>
#include <math.h>
#include <stdint.h>

#define D_MODEL 1024
#define S_LEN   2048
#define NHEAD   16
#define HDIM    64
#define MAXB    4
#define MMAX    (MAXB * S_LEN)

// ---------------- scratch (__device__ globals; no allocs allowed) ----------
__device__ __half g_xh [MMAX * D_MODEL];
__device__ __half g_xl [MMAX * D_MODEL];
__device__ __half g_aoh[MMAX * D_MODEL];
__device__ __half g_wh [4 * D_MODEL * D_MODEL];
__device__ __half g_wl [4 * D_MODEL * D_MODEL];
__device__ __half g_qh [MMAX * D_MODEL];
__device__ __half g_ql [MMAX * D_MODEL];
__device__ __half g_kh [MMAX * D_MODEL];
__device__ __half g_kl [MMAX * D_MODEL];
__device__ __half g_vh [MMAX * D_MODEL];
__device__ __half g_vl [MMAX * D_MODEL];
__device__ float g_ct[S_LEN * 32];
__device__ float g_st[S_LEN * 32];

// ---------------- helpers ----------------------------------------------------
__device__ __forceinline__ uint32_t smem_u32(const void* p) {
    uint32_t a;
    asm("{ .reg .u64 t; cvta.to.shared.u64 t, %1; cvt.u32.u64 %0, t; }" : "=r"(a) : "l"(p));
    return a;
}
__device__ __forceinline__ void cp_async16(uint32_t saddr, const void* gptr) {
    asm volatile("cp.async.cg.shared.global [%0], [%1], 16;" :: "r"(saddr), "l"(gptr));
}
__device__ __forceinline__ void ldmx4(uint32_t* r, uint32_t addr) {
    asm volatile("ldmatrix.sync.aligned.m8n8.x4.shared.b16 {%0,%1,%2,%3}, [%4];"
                 : "=r"(r[0]), "=r"(r[1]), "=r"(r[2]), "=r"(r[3]) : "r"(addr));
}
__device__ __forceinline__ void ldmx4t(uint32_t* r, uint32_t addr) {
    asm volatile("ldmatrix.sync.aligned.m8n8.x4.trans.shared.b16 {%0,%1,%2,%3}, [%4];"
                 : "=r"(r[0]), "=r"(r[1]), "=r"(r[2]), "=r"(r[3]) : "r"(addr));
}
__device__ __forceinline__ void mma16816(float* d, const uint32_t* a, const uint32_t* b) {
    asm volatile("mma.sync.aligned.m16n8k16.row.col.f32.f16.f16.f32 "
                 "{%0,%1,%2,%3}, {%4,%5,%6,%7}, {%8,%9}, {%0,%1,%2,%3};"
                 : "+f"(d[0]), "+f"(d[1]), "+f"(d[2]), "+f"(d[3])
                 : "r"(a[0]), "r"(a[1]), "r"(a[2]), "r"(a[3]), "r"(b[0]), "r"(b[1]));
}
__device__ __forceinline__ void store_split_pair(
    __half* H, __half* L, size_t off, float a, float b)
{
    __half2 hi = __floats2half2_rn(a, b);
    __half2 lo = __floats2half2_rn(a - __half2float(hi.x), b - __half2float(hi.y));
    *(__half2*)(H + off) = hi;
    *(__half2*)(L + off) = lo;
}

// ---------------- split fp32 -> fp16 hi/lo ----------------------------------
__global__ void split_kernel(const float* __restrict__ X,
                             __half* __restrict__ H,
                             __half* __restrict__ L, int n4)
{
    int i = blockIdx.x * blockDim.x + threadIdx.x;
    if (i >= n4) return;
    float4 v = ((const float4*)X)[i];
    __half2 hA = __floats2half2_rn(v.x, v.y);
    __half2 hB = __floats2half2_rn(v.z, v.w);
    __half2 lA = __floats2half2_rn(v.x - __half2float(hA.x), v.y - __half2float(hA.y));
    __half2 lB = __floats2half2_rn(v.z - __half2float(hB.x), v.w - __half2float(hB.y));
    uint2 hv, lv;
    hv.x = *(uint32_t*)&hA; hv.y = *(uint32_t*)&hB;
    lv.x = *(uint32_t*)&lA; lv.y = *(uint32_t*)&lB;
    ((uint2*)H)[i] = hv;
    ((uint2*)L)[i] = lv;
}

__global__ void split_w4(const float* __restrict__ W0, const float* __restrict__ W1,
                         const float* __restrict__ W2, const float* __restrict__ W3,
                         __half* __restrict__ H, __half* __restrict__ L, int n4)
{
    int i = blockIdx.x * blockDim.x + threadIdx.x;
    if (i >= n4) return;
    int z = blockIdx.y;
    const float* X = (z == 0) ? W0 : (z == 1) ? W1 : (z == 2) ? W2 : W3;
    float4 v = ((const float4*)X)[i];
    __half2 hA = __floats2half2_rn(v.x, v.y);
    __half2 hB = __floats2half2_rn(v.z, v.w);
    __half2 lA = __floats2half2_rn(v.x - __half2float(hA.x), v.y - __half2float(hA.y));
    __half2 lB = __floats2half2_rn(v.z - __half2float(hB.x), v.w - __half2float(hB.y));
    uint2 hv, lv;
    hv.x = *(uint32_t*)&hA; hv.y = *(uint32_t*)&hB;
    lv.x = *(uint32_t*)&lA; lv.y = *(uint32_t*)&lB;
    ((uint2*)(H + (size_t)z * D_MODEL * D_MODEL))[i] = hv;
    ((uint2*)(L + (size_t)z * D_MODEL * D_MODEL))[i] = lv;
}

// ---------------- RoPE cos/sin table ----------------------------------------
__global__ void rope_tab(float* __restrict__ ct, float* __restrict__ st)
{
    int idx = blockIdx.x * blockDim.x + threadIdx.x;
    if (idx >= S_LEN * 32) return;
    int s = idx >> 5, i = idx & 31;
    float inv = expf(-logf(10000.0f) * ((float)i / 32.0f));
    float sn, cs;
    sincosf((float)s * inv, &sn, &cs);
    ct[idx] = cs; st[idx] = sn;
}

// ---------------- GEMM core: 128x128, 2-stage ring, ONE sync per chunk ------
#define GSTRIDE 40
#define GARR    (128 * GSTRIDE * 2)      // 10240 B
#define GBUF    (4 * GARR)               // 40960 B per stage
#define G_SMEM_SZ (2 * GBUF)             // 81920 B -> 2 CTAs/SM

// compute one 32-wide K chunk; `three` selects 3-term vs 2-term split
__device__ __forceinline__ void gemm_chunk_compute(
    uint32_t boff, int lane, int warp_m, int warp_n, float acc[4][4][4], bool three)
{
    const int arow = warp_m * 64 + (lane & 15);
    const int brow_base = warp_n * 32 + ((lane >> 4) * 8) + (lane & 7);
    #pragma unroll
    for (int ks = 0; ks < 2; ++ks) {
        const int acol = ks * 16 + (lane >> 4) * 8;
        const int bcol = ks * 16 + ((lane >> 3) & 1) * 8;
        uint32_t bh[4][2], bl[4][2];
        #pragma unroll
        for (int g = 0; g < 2; ++g) {
            uint32_t addr = boff + 2 * GARR +
                            (uint32_t)((brow_base + g * 16) * GSTRIDE + bcol) * 2;
            uint32_t r[4];
            ldmx4(r, addr);
            bh[2*g][0] = r[0]; bh[2*g][1] = r[1];
            bh[2*g+1][0] = r[2]; bh[2*g+1][1] = r[3];
            ldmx4(r, addr + GARR);
            bl[2*g][0] = r[0]; bl[2*g][1] = r[1];
            bl[2*g+1][0] = r[2]; bl[2*g+1][1] = r[3];
        }
        #pragma unroll
        for (int half = 0; half < 2; ++half) {
            uint32_t ah[2][4], al[2][4];
            #pragma unroll
            for (int mi = 0; mi < 2; ++mi) {
                uint32_t addr = boff +
                    (uint32_t)((arow + (half * 2 + mi) * 16) * GSTRIDE + acol) * 2;
                ldmx4(ah[mi], addr);
                if (three) ldmx4(al[mi], addr + GARR);
            }
            #pragma unroll
            for (int mi = 0; mi < 2; ++mi)
                #pragma unroll
                for (int ni = 0; ni < 4; ++ni) {
                    float* a = acc[half * 2 + mi][ni];
                    mma16816(a, ah[mi], bh[ni]);
                    mma16816(a, ah[mi], bl[ni]);
                    if (three) mma16816(a, al[mi], bh[ni]);
                }
        }
    }
}

// ---------------- fused QKV mega-GEMM ----------------------------------------
__global__ __launch_bounds__(256, 2) void gemm_qkv(
    const __half* __restrict__ Ah, const __half* __restrict__ Al,
    const __half* __restrict__ Wh, const __half* __restrict__ Wl,
    __half* __restrict__ Qh, __half* __restrict__ Ql,
    __half* __restrict__ Kh, __half* __restrict__ Kl,
    __half* __restrict__ Vh, __half* __restrict__ Vl,
    const float* __restrict__ ct, const float* __restrict__ st,
    int M, int N, int K)
{
    extern __shared__ char smem[];
    const uint32_t sb = smem_u32(smem);
    const int tid = threadIdx.x;
    const int lane = tid & 31;
    const int wid = tid >> 5;
    const int warp_m = wid >> 2;
    const int warp_n = wid & 3;
    const int m0 = blockIdx.y * 128, n0 = blockIdx.x * 128;
    const int z = blockIdx.z;
    const bool three = (z < 2);          // V projection: 2-term suffices

    const __half* Bh = Wh + (size_t)z * K * N;
    const __half* Bl = Wl + (size_t)z * K * N;

    float acc[4][4][4] = {};
    const __half* srcs[4] = {Ah, Al, Bh, Bl};

    auto load_chunk = [&](int k0, int buf) {
        const uint32_t boff = sb + (uint32_t)buf * GBUF;
        #pragma unroll
        for (int p = 0; p < 4; ++p) {
            const __half* src = srcs[p];
            const int r0 = (p < 2) ? m0 : n0;
            const uint32_t abase = boff + (uint32_t)p * GARR;
            #pragma unroll
            for (int t = 0; t < 2; ++t) {
                int u = tid + t * 256;
                int row = u >> 2, c = (u & 3) * 8;
                cp_async16(abase + (uint32_t)(row * GSTRIDE + c) * 2,
                           src + (size_t)(r0 + row) * K + k0 + c);
            }
        }
        asm volatile("cp.async.commit_group;" ::: "memory");
    };

    load_chunk(0, 0);

    const int nch = K / 32;
    for (int c = 0; c < nch; ++c) {
        asm volatile("cp.async.wait_group 0;" ::: "memory");
        __syncthreads();
        if (c + 1 < nch) load_chunk((c + 1) * 32, (c + 1) & 1);
        gemm_chunk_compute(sb + (uint32_t)(c & 1) * GBUF, lane, warp_m, warp_n, acc, three);
    }

    __half* H = (z == 0) ? Qh : (z == 1) ? Kh : Vh;
    __half* L = (z == 0) ? Ql : (z == 1) ? Kl : Vl;
    const float qscale = (z == 0) ? 0.125f : 1.0f;

    #pragma unroll
    for (int mi = 0; mi < 4; ++mi) {
        const int r = m0 + warp_m * 64 + mi * 16 + (lane >> 2);
        const int s0 = r & (S_LEN - 1);
        const int s1 = (r + 8) & (S_LEN - 1);
        #pragma unroll
        for (int ni = 0; ni < 4; ++ni) {
            const int cidx = n0 + warp_n * 32 + ni * 8 + (lane & 3) * 2;
            float a0 = acc[mi][ni][0], a1 = acc[mi][ni][1];
            float b0 = acc[mi][ni][2], b1 = acc[mi][ni][3];
            if (z < 2) {
                const int i = (cidx & (HDIM - 1)) >> 1;
                float c0 = ct[s0 * 32 + i], sn0 = st[s0 * 32 + i];
                float c1 = ct[s1 * 32 + i], sn1 = st[s1 * 32 + i];
                float e = a0, o = a1;
                a0 = (e * c0 - o * sn0) * qscale;
                a1 = (e * sn0 + o * c0) * qscale;
                e = b0; o = b1;
                b0 = (e * c1 - o * sn1) * qscale;
                b1 = (e * sn1 + o * c1) * qscale;
            }
            store_split_pair(H, L, (size_t)r * N + cidx, a0, a1);
            store_split_pair(H, L, (size_t)(r + 8) * N + cidx, b0, b1);
        }
    }
}

// ---------------- plain GEMM (final O-proj, 2-term) ---------------------------
__global__ __launch_bounds__(256, 2) void gemm_mma(
    const __half* __restrict__ Ah, const __half* __restrict__ Al,
    const __half* __restrict__ Bh, const __half* __restrict__ Bl,
    float* __restrict__ C, int M, int N, int K)
{
    extern __shared__ char smem[];
    const uint32_t sb = smem_u32(smem);
    const int tid = threadIdx.x;
    const int lane = tid & 31;
    const int wid = tid >> 5;
    const int warp_m = wid >> 2;
    const int warp_n = wid & 3;
    const int m0 = blockIdx.y * 128, n0 = blockIdx.x * 128;

    float acc[4][4][4] = {};
    const __half* srcs[4] = {Ah, Al, Bh, Bl};

    auto load_chunk = [&](int k0, int buf) {
        const uint32_t boff = sb + (uint32_t)buf * GBUF;
        #pragma unroll
        for (int p = 0; p < 4; ++p) {
            const __half* src = srcs[p];
            const int r0 = (p < 2) ? m0 : n0;
            const uint32_t abase = boff + (uint32_t)p * GARR;
            #pragma unroll
            for (int t = 0; t < 2; ++t) {
                int u = tid + t * 256;
                int row = u >> 2, c = (u & 3) * 8;
                cp_async16(abase + (uint32_t)(row * GSTRIDE + c) * 2,
                           src + (size_t)(r0 + row) * K + k0 + c);
            }
        }
        asm volatile("cp.async.commit_group;" ::: "memory");
    };

    load_chunk(0, 0);

    const int nch = K / 32;
    for (int c = 0; c < nch; ++c) {
        asm volatile("cp.async.wait_group 0;" ::: "memory");
        __syncthreads();
        if (c + 1 < nch) load_chunk((c + 1) * 32, (c + 1) & 1);
        gemm_chunk_compute(sb + (uint32_t)(c & 1) * GBUF, lane, warp_m, warp_n, acc, false);
    }

    #pragma unroll
    for (int mi = 0; mi < 4; ++mi) {
        const int r = m0 + warp_m * 64 + mi * 16 + (lane >> 2);
        #pragma unroll
        for (int ni = 0; ni < 4; ++ni) {
            const int cidx = n0 + warp_n * 32 + ni * 8 + (lane & 3) * 2;
            float2 v0 = {acc[mi][ni][0], acc[mi][ni][1]};
            float2 v1 = {acc[mi][ni][2], acc[mi][ni][3]};
            *(float2*)(C + (size_t)r * N + cidx)       = v0;
            *(float2*)(C + (size_t)(r + 8) * N + cidx) = v1;
        }
    }
}

// ---------------- persistent, statically-balanced causal flash --------------
#define FSTR   72
#define FARR   (64 * FSTR * 2)          // 9216 B
#define FSTAGE (4 * FARR)               // 36864 B (Kh,Kl,Vh,Vl)
#define FQARR  (256 * FSTR * 2)         // 36864 B
#define FKVOFF (2 * FQARR)              // 73728
#define F_SMEM (FKVOFF + 3 * FSTAGE)    // 184320 B

__global__ __launch_bounds__(256, 1) void flash_mma(
    const __half* __restrict__ Qh_, const __half* __restrict__ Ql_,
    const __half* __restrict__ Kh_, const __half* __restrict__ Kl_,
    const __half* __restrict__ Vh_, const __half* __restrict__ Vl_,
    __half* __restrict__ AOh, int NB)
{
    extern __shared__ char smem[];
    const uint32_t sb = smem_u32(smem);
    const int tid = threadIdx.x, lane = tid & 31, w = tid >> 5;
    const int p = blockIdx.x;

    const __half* kv_src[4] = {Kh_, Kl_, Vh_, Vl_};

    #pragma unroll 1
    for (int pass = 0; pass < 4; ++pass) {
        int s;
        switch (pass) {
            case 0:  s = p;              break;
            case 1:  s = 4 * NB - 1 - p; break;
            case 2:  s = 4 * NB + p;     break;
            default: s = 8 * NB - 1 - p; break;
        }
        const int bx = s / NB;
        const int r_ = s % NB;
        const int h = r_ & (NHEAD - 1);
        const int b = r_ >> 4;
        const int q0 = bx * 256;

        __syncthreads();

        const size_t base_q = (size_t)(b * S_LEN + q0) * D_MODEL + h * HDIM;
        #pragma unroll
        for (int t = 0; t < 8; ++t) {
            int idx = tid + t * 256;
            int r = idx >> 3, c = (idx & 7) * 8;
            cp_async16(sb + (uint32_t)(r * FSTR + c) * 2,
                       Qh_ + base_q + (size_t)r * D_MODEL + c);
            cp_async16(sb + FQARR + (uint32_t)(r * FSTR + c) * 2,
                       Ql_ + base_q + (size_t)r * D_MODEL + c);
        }
        asm volatile("cp.async.commit_group;" ::: "memory");

        auto load_kv = [&](int j, int st) {
            const size_t gb = (size_t)(b * S_LEN + j * 64) * D_MODEL + h * HDIM;
            const uint32_t sbase = sb + FKVOFF + (uint32_t)st * FSTAGE;
            #pragma unroll
            for (int pp = 0; pp < 4; ++pp) {
                #pragma unroll
                for (int t = 0; t < 2; ++t) {
                    int idx = tid + t * 256;
                    int r = idx >> 3, c = (idx & 7) * 8;
                    cp_async16(sbase + (uint32_t)pp * FARR + (uint32_t)(r * FSTR + c) * 2,
                               kv_src[pp] + gb + (size_t)r * D_MODEL + c);
                }
            }
            asm volatile("cp.async.commit_group;" ::: "memory");
        };

        const int jend = 4 * bx + 4;
        load_kv(0, 0);
        if (jend > 1) load_kv(1, 1);

        float o[2][8][4] = {};
        float mrow[2][2] = {{-1e30f, -1e30f}, {-1e30f, -1e30f}};
        float lrow[2][2] = {};

        for (int j = 0; j < jend; ++j) {
            if (j + 1 < jend) {
                asm volatile("cp.async.wait_group 1;" ::: "memory");
            } else {
                asm volatile("cp.async.wait_group 0;" ::: "memory");
            }
            __syncthreads();
            if (j + 2 < jend) load_kv(j + 2, (j + 2) % 3);

            const int k0 = j * 64;
            if (k0 <= q0 + w * 32 + 31) {
                const uint32_t sbase = sb + FKVOFF + (uint32_t)(j % 3) * FSTAGE;

                float sreg[2][8][4] = {};
                #pragma unroll
                for (int ks = 0; ks < 4; ++ks) {
                    uint32_t bh[8][2], bl[8][2];
                    #pragma unroll
                    for (int g = 0; g < 4; ++g) {
                        const int row = g * 16 + (lane >> 4) * 8 + (lane & 7);
                        const int col = ks * 16 + ((lane >> 3) & 1) * 8;
                        uint32_t addr = sbase + (uint32_t)(row * FSTR + col) * 2;
                        uint32_t r4[4];
                        ldmx4(r4, addr);
                        bh[2*g][0]=r4[0]; bh[2*g][1]=r4[1]; bh[2*g+1][0]=r4[2]; bh[2*g+1][1]=r4[3];
                        ldmx4(r4, addr + FARR);
                        bl[2*g][0]=r4[0]; bl[2*g][1]=r4[1]; bl[2*g+1][0]=r4[2]; bl[2*g+1][1]=r4[3];
                    }
                    #pragma unroll
                    for (int mf = 0; mf < 2; ++mf) {
                        const int qrow = w * 32 + mf * 16 + (lane & 15);
                        const int qcol = ks * 16 + (lane >> 4) * 8;
                        uint32_t qaddr = sb + (uint32_t)(qrow * FSTR + qcol) * 2;
                        uint32_t qhf[4], qlf[4];
                        ldmx4(qhf, qaddr);
                        ldmx4(qlf, qaddr + FQARR);
                        #pragma unroll
                        for (int n = 0; n < 8; ++n) mma16816(sreg[mf][n], qhf, bh[n]);
                        #pragma unroll
                        for (int n = 0; n < 8; ++n) mma16816(sreg[mf][n], qhf, bl[n]);
                        #pragma unroll
                        for (int n = 0; n < 8; ++n) mma16816(sreg[mf][n], qlf, bh[n]);
                    }
                }

                uint32_t ph[2][2][8];
                float a[2][2];
                #pragma unroll
                for (int mf = 0; mf < 2; ++mf) {
                    const int gr = q0 + w * 32 + mf * 16 + (lane >> 2);
                    if (k0 + 63 > q0 + w * 32 + mf * 16) {
                        #pragma unroll
                        for (int t = 0; t < 8; ++t) {
                            int c = k0 + t * 8 + 2 * (lane & 3);
                            if (c     > gr)     sreg[mf][t][0] = -1e30f;
                            if (c + 1 > gr)     sreg[mf][t][1] = -1e30f;
                            if (c     > gr + 8) sreg[mf][t][2] = -1e30f;
                            if (c + 1 > gr + 8) sreg[mf][t][3] = -1e30f;
                        }
                    }
                    float mx0 = -1e30f, mx1 = -1e30f;
                    #pragma unroll
                    for (int t = 0; t < 8; ++t) {
                        mx0 = fmaxf(mx0, fmaxf(sreg[mf][t][0], sreg[mf][t][1]));
                        mx1 = fmaxf(mx1, fmaxf(sreg[mf][t][2], sreg[mf][t][3]));
                    }
                    mx0 = fmaxf(mx0, __shfl_xor_sync(0xffffffffu, mx0, 1));
                    mx0 = fmaxf(mx0, __shfl_xor_sync(0xffffffffu, mx0, 2));
                    mx1 = fmaxf(mx1, __shfl_xor_sync(0xffffffffu, mx1, 1));
                    mx1 = fmaxf(mx1, __shfl_xor_sync(0xffffffffu, mx1, 2));
                    const float mn0 = fmaxf(mrow[mf][0], mx0), mn1 = fmaxf(mrow[mf][1], mx1);
                    a[mf][0] = __expf(mrow[mf][0] - mn0);
                    a[mf][1] = __expf(mrow[mf][1] - mn1);
                    mrow[mf][0] = mn0; mrow[mf][1] = mn1;

                    float ps0 = 0.0f, ps1 = 0.0f;
                    #pragma unroll
                    for (int t = 0; t < 8; ++t) {
                        float p0 = __expf(sreg[mf][t][0] - mn0), p1 = __expf(sreg[mf][t][1] - mn0);
                        float p2 = __expf(sreg[mf][t][2] - mn1), p3 = __expf(sreg[mf][t][3] - mn1);
                        ps0 += p0 + p1; ps1 += p2 + p3;
                        __half2 h01 = __floats2half2_rn(p0, p1);
                        __half2 h23 = __floats2half2_rn(p2, p3);
                        ph[mf][0][t] = *(uint32_t*)&h01;
                        ph[mf][1][t] = *(uint32_t*)&h23;
                    }
                    ps0 += __shfl_xor_sync(0xffffffffu, ps0, 1);
                    ps0 += __shfl_xor_sync(0xffffffffu, ps0, 2);
                    ps1 += __shfl_xor_sync(0xffffffffu, ps1, 1);
                    ps1 += __shfl_xor_sync(0xffffffffu, ps1, 2);
                    lrow[mf][0] = lrow[mf][0] * a[mf][0] + ps0;
                    lrow[mf][1] = lrow[mf][1] * a[mf][1] + ps1;

                    #pragma unroll
                    for (int t = 0; t < 8; ++t) {
                        o[mf][t][0] *= a[mf][0]; o[mf][t][1] *= a[mf][0];
                        o[mf][t][2] *= a[mf][1]; o[mf][t][3] *= a[mf][1];
                    }
                }

                #pragma unroll
                for (int ks = 0; ks < 4; ++ks) {
                    uint32_t bvh[8][2], bvl[8][2];
                    #pragma unroll
                    for (int g = 0; g < 4; ++g) {
                        const int row = ks * 16 + (lane & 15);
                        const int col = g * 16 + (lane >> 4) * 8;
                        uint32_t addr = sbase + 2u * FARR + (uint32_t)(row * FSTR + col) * 2;
                        uint32_t r4[4];
                        ldmx4t(r4, addr);
                        bvh[2*g][0]=r4[0]; bvh[2*g][1]=r4[1]; bvh[2*g+1][0]=r4[2]; bvh[2*g+1][1]=r4[3];
                        ldmx4t(r4, addr + FARR);
                        bvl[2*g][0]=r4[0]; bvl[2*g][1]=r4[1]; bvl[2*g+1][0]=r4[2]; bvl[2*g+1][1]=r4[3];
                    }
                    #pragma unroll
                    for (int mf = 0; mf < 2; ++mf) {
                        uint32_t pah[4] = {ph[mf][0][2*ks], ph[mf][1][2*ks],
                                           ph[mf][0][2*ks+1], ph[mf][1][2*ks+1]};
                        #pragma unroll
                        for (int n = 0; n < 8; ++n) mma16816(o[mf][n], pah, bvh[n]);
                        #pragma unroll
                        for (int n = 0; n < 8; ++n) mma16816(o[mf][n], pah, bvl[n]);
                    }
                }
            }
        }

        // epilogue: normalize, store fp16 hi only (O-proj is 2-term)
        const size_t ob = (size_t)b * S_LEN * D_MODEL + h * HDIM;
        #pragma unroll
        for (int mf = 0; mf < 2; ++mf) {
            const float inv0 = 1.0f / lrow[mf][0], inv1 = 1.0f / lrow[mf][1];
            const int gr = q0 + w * 32 + mf * 16 + (lane >> 2);
            #pragma unroll
            for (int t = 0; t < 8; ++t) {
                const int c = t * 8 + 2 * (lane & 3);
                __half2 v0 = __floats2half2_rn(o[mf][t][0] * inv0, o[mf][t][1] * inv0);
                __half2 v1 = __floats2half2_rn(o[mf][t][2] * inv1, o[mf][t][3] * inv1);
                *(__half2*)(AOh + ob + (size_t)gr * D_MODEL + c)       = v0;
                *(__half2*)(AOh + ob + (size_t)(gr + 8) * D_MODEL + c) = v1;
            }
        }
    }
}

// ---------------------------------------------------------------------------
extern "C" void kernel_launch(void* const* d_in, const int* in_sizes, int n_in,
                              void* d_out, int out_size)
{
    const float* x  = (const float*)d_in[0];
    const float* qw = (const float*)d_in[1];
    const float* kw = (const float*)d_in[2];
    const float* vw = (const float*)d_in[3];
    const float* ow = (const float*)d_in[4];

    const int M = in_sizes[0] / D_MODEL;
    const int B = M / S_LEN;
    const int W = D_MODEL * D_MODEL;

    void *pxh, *pxl, *pah, *pwh, *pwl;
    void *pqh, *pql, *pkh, *pkl, *pvh, *pvl, *pct, *pst;
    cudaGetSymbolAddress(&pxh, g_xh);  cudaGetSymbolAddress(&pxl, g_xl);
    cudaGetSymbolAddress(&pah, g_aoh);
    cudaGetSymbolAddress(&pwh, g_wh);  cudaGetSymbolAddress(&pwl, g_wl);
    cudaGetSymbolAddress(&pqh, g_qh);  cudaGetSymbolAddress(&pql, g_ql);
    cudaGetSymbolAddress(&pkh, g_kh);  cudaGetSymbolAddress(&pkl, g_kl);
    cudaGetSymbolAddress(&pvh, g_vh);  cudaGetSymbolAddress(&pvl, g_vl);
    cudaGetSymbolAddress(&pct, g_ct);  cudaGetSymbolAddress(&pst, g_st);
    __half* xh = (__half*)pxh;  __half* xl = (__half*)pxl;
    __half* aoh = (__half*)pah;
    __half* wh = (__half*)pwh;  __half* wl = (__half*)pwl;
    __half* qhp = (__half*)pqh; __half* qlp = (__half*)pql;
    __half* khp = (__half*)pkh; __half* klp = (__half*)pkl;
    __half* vhp = (__half*)pvh; __half* vlp = (__half*)pvl;
    float* ct = (float*)pct; float* st = (float*)pst;

    int n4x = M * D_MODEL / 4;
    split_kernel<<<(n4x + 255) / 256, 256>>>(x, xh, xl, n4x);
    int n4w = W / 4;
    dim3 wgrid((n4w + 255) / 256, 4);
    split_w4<<<wgrid, 256>>>(qw, kw, vw, ow, wh, wl, n4w);
    rope_tab<<<(S_LEN * 32 + 255) / 256, 256>>>(ct, st);

    cudaFuncSetAttribute(gemm_qkv, cudaFuncAttributeMaxDynamicSharedMemorySize, G_SMEM_SZ);
    dim3 qkvgrid(D_MODEL / 128, M / 128, 3);
    gemm_qkv<<<qkvgrid, 256, G_SMEM_SZ>>>(xh, xl, wh, wl,
                                          qhp, qlp, khp, klp, vhp, vlp,
                                          ct, st, M, D_MODEL, D_MODEL);

    cudaFuncSetAttribute(flash_mma, cudaFuncAttributeMaxDynamicSharedMemorySize, F_SMEM);
    const int NB = NHEAD * B;
    flash_mma<<<2 * NB, 256, F_SMEM>>>(qhp, qlp, khp, klp, vhp, vlp, aoh, NB);

    cudaFuncSetAttribute(gemm_mma, cudaFuncAttributeMaxDynamicSharedMemorySize, G_SMEM_SZ);
    dim3 ggrid(D_MODEL / 128, M / 128);
    gemm_mma<<<ggrid, 256, G_SMEM_SZ>>>(aoh, aoh, wh + 3 * W, wl + 3 * W,
                                        (float*)d_out, M, D_MODEL, D_MODEL);
}

// round 16
// speedup vs baseline: 1.1677x; 1.0298x over previous
#include <cuda_runtime.h>
#include <cuda_fp16.h>
#include <math.h>
#include <stdint.h>

#define D_MODEL 1024
#define S_LEN   2048
#define NHEAD   16
#define HDIM    64
#define MAXB    4
#define MMAX    (MAXB * S_LEN)

// ---------------- scratch (__device__ globals; no allocs allowed) ----------
__device__ __half g_xh [MMAX * D_MODEL];
__device__ __half g_xl [MMAX * D_MODEL];
__device__ __half g_aoh[MMAX * D_MODEL];
__device__ __half g_wh [4 * D_MODEL * D_MODEL];
__device__ __half g_wl [4 * D_MODEL * D_MODEL];
__device__ __half g_qh [MMAX * D_MODEL];
__device__ __half g_ql [MMAX * D_MODEL];
__device__ __half g_kh [MMAX * D_MODEL];
__device__ __half g_kl [MMAX * D_MODEL];
__device__ __half g_vh [MMAX * D_MODEL];
__device__ __half g_vl [MMAX * D_MODEL];
__device__ float g_ct[S_LEN * 32];
__device__ float g_st[S_LEN * 32];

// ---------------- helpers ----------------------------------------------------
__device__ __forceinline__ uint32_t smem_u32(const void* p) {
    uint32_t a;
    asm("{ .reg .u64 t; cvta.to.shared.u64 t, %1; cvt.u32.u64 %0, t; }" : "=r"(a) : "l"(p));
    return a;
}
__device__ __forceinline__ void cp_async16(uint32_t saddr, const void* gptr) {
    asm volatile("cp.async.cg.shared.global [%0], [%1], 16;" :: "r"(saddr), "l"(gptr));
}
__device__ __forceinline__ void ldmx4(uint32_t* r, uint32_t addr) {
    asm volatile("ldmatrix.sync.aligned.m8n8.x4.shared.b16 {%0,%1,%2,%3}, [%4];"
                 : "=r"(r[0]), "=r"(r[1]), "=r"(r[2]), "=r"(r[3]) : "r"(addr));
}
__device__ __forceinline__ void ldmx4t(uint32_t* r, uint32_t addr) {
    asm volatile("ldmatrix.sync.aligned.m8n8.x4.trans.shared.b16 {%0,%1,%2,%3}, [%4];"
                 : "=r"(r[0]), "=r"(r[1]), "=r"(r[2]), "=r"(r[3]) : "r"(addr));
}
__device__ __forceinline__ void mma16816(float* d, const uint32_t* a, const uint32_t* b) {
    asm volatile("mma.sync.aligned.m16n8k16.row.col.f32.f16.f16.f32 "
                 "{%0,%1,%2,%3}, {%4,%5,%6,%7}, {%8,%9}, {%0,%1,%2,%3};"
                 : "+f"(d[0]), "+f"(d[1]), "+f"(d[2]), "+f"(d[3])
                 : "r"(a[0]), "r"(a[1]), "r"(a[2]), "r"(a[3]), "r"(b[0]), "r"(b[1]));
}
__device__ __forceinline__ void store_split_pair(
    __half* H, __half* L, size_t off, float a, float b)
{
    __half2 hi = __floats2half2_rn(a, b);
    __half2 lo = __floats2half2_rn(a - __half2float(hi.x), b - __half2float(hi.y));
    *(__half2*)(H + off) = hi;
    *(__half2*)(L + off) = lo;
}

// ---------------- split fp32 -> fp16 hi/lo ----------------------------------
__global__ void split_kernel(const float* __restrict__ X,
                             __half* __restrict__ H,
                             __half* __restrict__ L, int n4)
{
    int i = blockIdx.x * blockDim.x + threadIdx.x;
    if (i >= n4) return;
    float4 v = ((const float4*)X)[i];
    __half2 hA = __floats2half2_rn(v.x, v.y);
    __half2 hB = __floats2half2_rn(v.z, v.w);
    __half2 lA = __floats2half2_rn(v.x - __half2float(hA.x), v.y - __half2float(hA.y));
    __half2 lB = __floats2half2_rn(v.z - __half2float(hB.x), v.w - __half2float(hB.y));
    uint2 hv, lv;
    hv.x = *(uint32_t*)&hA; hv.y = *(uint32_t*)&hB;
    lv.x = *(uint32_t*)&lA; lv.y = *(uint32_t*)&lB;
    ((uint2*)H)[i] = hv;
    ((uint2*)L)[i] = lv;
}

__global__ void split_w4(const float* __restrict__ W0, const float* __restrict__ W1,
                         const float* __restrict__ W2, const float* __restrict__ W3,
                         __half* __restrict__ H, __half* __restrict__ L, int n4)
{
    int i = blockIdx.x * blockDim.x + threadIdx.x;
    if (i >= n4) return;
    int z = blockIdx.y;
    const float* X = (z == 0) ? W0 : (z == 1) ? W1 : (z == 2) ? W2 : W3;
    float4 v = ((const float4*)X)[i];
    __half2 hA = __floats2half2_rn(v.x, v.y);
    __half2 hB = __floats2half2_rn(v.z, v.w);
    __half2 lA = __floats2half2_rn(v.x - __half2float(hA.x), v.y - __half2float(hA.y));
    __half2 lB = __floats2half2_rn(v.z - __half2float(hB.x), v.w - __half2float(hB.y));
    uint2 hv, lv;
    hv.x = *(uint32_t*)&hA; hv.y = *(uint32_t*)&hB;
    lv.x = *(uint32_t*)&lA; lv.y = *(uint32_t*)&lB;
    ((uint2*)(H + (size_t)z * D_MODEL * D_MODEL))[i] = hv;
    ((uint2*)(L + (size_t)z * D_MODEL * D_MODEL))[i] = lv;
}

// ---------------- RoPE cos/sin table ----------------------------------------
__global__ void rope_tab(float* __restrict__ ct, float* __restrict__ st)
{
    int idx = blockIdx.x * blockDim.x + threadIdx.x;
    if (idx >= S_LEN * 32) return;
    int s = idx >> 5, i = idx & 31;
    float inv = expf(-logf(10000.0f) * ((float)i / 32.0f));
    float sn, cs;
    sincosf((float)s * inv, &sn, &cs);
    ct[idx] = cs; st[idx] = sn;
}

// ---------------- GEMM core: 128x128, 2-stage ring ---------------------------
// slots: 0 = A-hi, 1 = A-lo (3-term only), 2 = B-hi, 3 = B-lo
#define GSTRIDE 40
#define GARR    (128 * GSTRIDE * 2)      // 10240 B
#define GBUF    (4 * GARR)               // 40960 B per stage
#define G_SMEM_SZ (2 * GBUF)             // 81920 B -> 2 CTAs/SM

__device__ __forceinline__ void gemm_chunk_compute(
    uint32_t boff, int lane, int warp_m, int warp_n, float acc[4][4][4], bool three)
{
    const int arow = warp_m * 64 + (lane & 15);
    const int brow_base = warp_n * 32 + ((lane >> 4) * 8) + (lane & 7);
    #pragma unroll
    for (int ks = 0; ks < 2; ++ks) {
        const int acol = ks * 16 + (lane >> 4) * 8;
        const int bcol = ks * 16 + ((lane >> 3) & 1) * 8;
        uint32_t bh[4][2], bl[4][2];
        #pragma unroll
        for (int g = 0; g < 2; ++g) {
            uint32_t addr = boff + 2 * GARR +
                            (uint32_t)((brow_base + g * 16) * GSTRIDE + bcol) * 2;
            uint32_t r[4];
            ldmx4(r, addr);
            bh[2*g][0] = r[0]; bh[2*g][1] = r[1];
            bh[2*g+1][0] = r[2]; bh[2*g+1][1] = r[3];
            ldmx4(r, addr + GARR);
            bl[2*g][0] = r[0]; bl[2*g][1] = r[1];
            bl[2*g+1][0] = r[2]; bl[2*g+1][1] = r[3];
        }
        #pragma unroll
        for (int half = 0; half < 2; ++half) {
            uint32_t ah[2][4], al[2][4];
            #pragma unroll
            for (int mi = 0; mi < 2; ++mi) {
                uint32_t addr = boff +
                    (uint32_t)((arow + (half * 2 + mi) * 16) * GSTRIDE + acol) * 2;
                ldmx4(ah[mi], addr);
                if (three) ldmx4(al[mi], addr + GARR);
            }
            #pragma unroll
            for (int mi = 0; mi < 2; ++mi)
                #pragma unroll
                for (int ni = 0; ni < 4; ++ni) {
                    float* a = acc[half * 2 + mi][ni];
                    mma16816(a, ah[mi], bh[ni]);
                    mma16816(a, ah[mi], bl[ni]);
                    if (three) mma16816(a, al[mi], bh[ni]);
                }
        }
    }
}

// ---------------- fused QKV mega-GEMM (Q/K 3-term, V 2-term) -----------------
__global__ __launch_bounds__(256, 2) void gemm_qkv(
    const __half* __restrict__ Ah, const __half* __restrict__ Al,
    const __half* __restrict__ Wh, const __half* __restrict__ Wl,
    __half* __restrict__ Qh, __half* __restrict__ Ql,
    __half* __restrict__ Kh, __half* __restrict__ Kl,
    __half* __restrict__ Vh, __half* __restrict__ Vl,
    const float* __restrict__ ct, const float* __restrict__ st,
    int M, int N, int K)
{
    extern __shared__ char smem[];
    const uint32_t sb = smem_u32(smem);
    const int tid = threadIdx.x;
    const int lane = tid & 31;
    const int wid = tid >> 5;
    const int warp_m = wid >> 2;
    const int warp_n = wid & 3;
    const int m0 = blockIdx.y * 128, n0 = blockIdx.x * 128;
    const int z = blockIdx.z;
    const bool three = (z < 2);

    const __half* Bh = Wh + (size_t)z * K * N;
    const __half* Bl = Wl + (size_t)z * K * N;

    float acc[4][4][4] = {};
    const __half* srcs[4] = {Ah, Al, Bh, Bl};

    auto load_chunk = [&](int k0, int buf) {
        const uint32_t boff = sb + (uint32_t)buf * GBUF;
        #pragma unroll
        for (int p = 0; p < 4; ++p) {
            if (p == 1 && !three) continue;     // skip A-lo fill for 2-term blocks
            const __half* src = srcs[p];
            const int r0 = (p < 2) ? m0 : n0;
            const uint32_t abase = boff + (uint32_t)p * GARR;
            #pragma unroll
            for (int t = 0; t < 2; ++t) {
                int u = tid + t * 256;
                int row = u >> 2, c = (u & 3) * 8;
                cp_async16(abase + (uint32_t)(row * GSTRIDE + c) * 2,
                           src + (size_t)(r0 + row) * K + k0 + c);
            }
        }
        asm volatile("cp.async.commit_group;" ::: "memory");
    };

    load_chunk(0, 0);

    const int nch = K / 32;
    for (int c = 0; c < nch; ++c) {
        asm volatile("cp.async.wait_group 0;" ::: "memory");
        __syncthreads();
        if (c + 1 < nch) load_chunk((c + 1) * 32, (c + 1) & 1);
        gemm_chunk_compute(sb + (uint32_t)(c & 1) * GBUF, lane, warp_m, warp_n, acc, three);
    }

    __half* H = (z == 0) ? Qh : (z == 1) ? Kh : Vh;
    __half* L = (z == 0) ? Ql : (z == 1) ? Kl : Vl;
    const float qscale = (z == 0) ? 0.125f : 1.0f;

    #pragma unroll
    for (int mi = 0; mi < 4; ++mi) {
        const int r = m0 + warp_m * 64 + mi * 16 + (lane >> 2);
        const int s0 = r & (S_LEN - 1);
        const int s1 = (r + 8) & (S_LEN - 1);
        #pragma unroll
        for (int ni = 0; ni < 4; ++ni) {
            const int cidx = n0 + warp_n * 32 + ni * 8 + (lane & 3) * 2;
            float a0 = acc[mi][ni][0], a1 = acc[mi][ni][1];
            float b0 = acc[mi][ni][2], b1 = acc[mi][ni][3];
            if (z < 2) {
                const int i = (cidx & (HDIM - 1)) >> 1;
                float c0 = ct[s0 * 32 + i], sn0 = st[s0 * 32 + i];
                float c1 = ct[s1 * 32 + i], sn1 = st[s1 * 32 + i];
                float e = a0, o = a1;
                a0 = (e * c0 - o * sn0) * qscale;
                a1 = (e * sn0 + o * c0) * qscale;
                e = b0; o = b1;
                b0 = (e * c1 - o * sn1) * qscale;
                b1 = (e * sn1 + o * c1) * qscale;
            }
            store_split_pair(H, L, (size_t)r * N + cidx, a0, a1);
            store_split_pair(H, L, (size_t)(r + 8) * N + cidx, b0, b1);
        }
    }
}

// ---------------- plain GEMM (final O-proj, 2-term) ---------------------------
__global__ __launch_bounds__(256, 2) void gemm_mma(
    const __half* __restrict__ Ah,
    const __half* __restrict__ Bh, const __half* __restrict__ Bl,
    float* __restrict__ C, int M, int N, int K)
{
    extern __shared__ char smem[];
    const uint32_t sb = smem_u32(smem);
    const int tid = threadIdx.x;
    const int lane = tid & 31;
    const int wid = tid >> 5;
    const int warp_m = wid >> 2;
    const int warp_n = wid & 3;
    const int m0 = blockIdx.y * 128, n0 = blockIdx.x * 128;

    float acc[4][4][4] = {};
    const __half* srcs[3] = {Ah, Bh, Bl};
    const uint32_t slot[3] = {0, 2, 3};

    auto load_chunk = [&](int k0, int buf) {
        const uint32_t boff = sb + (uint32_t)buf * GBUF;
        #pragma unroll
        for (int p = 0; p < 3; ++p) {
            const __half* src = srcs[p];
            const int r0 = (p == 0) ? m0 : n0;
            const uint32_t abase = boff + slot[p] * GARR;
            #pragma unroll
            for (int t = 0; t < 2; ++t) {
                int u = tid + t * 256;
                int row = u >> 2, c = (u & 3) * 8;
                cp_async16(abase + (uint32_t)(row * GSTRIDE + c) * 2,
                           src + (size_t)(r0 + row) * K + k0 + c);
            }
        }
        asm volatile("cp.async.commit_group;" ::: "memory");
    };

    load_chunk(0, 0);

    const int nch = K / 32;
    for (int c = 0; c < nch; ++c) {
        asm volatile("cp.async.wait_group 0;" ::: "memory");
        __syncthreads();
        if (c + 1 < nch) load_chunk((c + 1) * 32, (c + 1) & 1);
        gemm_chunk_compute(sb + (uint32_t)(c & 1) * GBUF, lane, warp_m, warp_n, acc, false);
    }

    #pragma unroll
    for (int mi = 0; mi < 4; ++mi) {
        const int r = m0 + warp_m * 64 + mi * 16 + (lane >> 2);
        #pragma unroll
        for (int ni = 0; ni < 4; ++ni) {
            const int cidx = n0 + warp_n * 32 + ni * 8 + (lane & 3) * 2;
            float2 v0 = {acc[mi][ni][0], acc[mi][ni][1]};
            float2 v1 = {acc[mi][ni][2], acc[mi][ni][3]};
            *(float2*)(C + (size_t)r * N + cidx)       = v0;
            *(float2*)(C + (size_t)(r + 8) * N + cidx) = v1;
        }
    }
}

// ---------------- persistent, statically-balanced causal flash --------------
#define FSTR   72
#define FARR   (64 * FSTR * 2)          // 9216 B
#define FSTAGE (4 * FARR)               // 36864 B (Kh,Kl,Vh,Vl)
#define FQARR  (256 * FSTR * 2)         // 36864 B
#define FKVOFF (2 * FQARR)              // 73728
#define F_SMEM (FKVOFF + 3 * FSTAGE)    // 184320 B

__global__ __launch_bounds__(256, 1) void flash_mma(
    const __half* __restrict__ Qh_, const __half* __restrict__ Ql_,
    const __half* __restrict__ Kh_, const __half* __restrict__ Kl_,
    const __half* __restrict__ Vh_, const __half* __restrict__ Vl_,
    __half* __restrict__ AOh, int NB)
{
    extern __shared__ char smem[];
    const uint32_t sb = smem_u32(smem);
    const int tid = threadIdx.x, lane = tid & 31, w = tid >> 5;
    const int p = blockIdx.x;

    const __half* kv_src[4] = {Kh_, Kl_, Vh_, Vl_};

    #pragma unroll 1
    for (int pass = 0; pass < 4; ++pass) {
        int s;
        switch (pass) {
            case 0:  s = p;              break;
            case 1:  s = 4 * NB - 1 - p; break;
            case 2:  s = 4 * NB + p;     break;
            default: s = 8 * NB - 1 - p; break;
        }
        const int bx = s / NB;
        const int r_ = s % NB;
        const int h = r_ & (NHEAD - 1);
        const int b = r_ >> 4;
        const int q0 = bx * 256;

        __syncthreads();

        const size_t base_q = (size_t)(b * S_LEN + q0) * D_MODEL + h * HDIM;
        #pragma unroll
        for (int t = 0; t < 8; ++t) {
            int idx = tid + t * 256;
            int r = idx >> 3, c = (idx & 7) * 8;
            cp_async16(sb + (uint32_t)(r * FSTR + c) * 2,
                       Qh_ + base_q + (size_t)r * D_MODEL + c);
            cp_async16(sb + FQARR + (uint32_t)(r * FSTR + c) * 2,
                       Ql_ + base_q + (size_t)r * D_MODEL + c);
        }
        asm volatile("cp.async.commit_group;" ::: "memory");

        auto load_kv = [&](int j, int st) {
            const size_t gb = (size_t)(b * S_LEN + j * 64) * D_MODEL + h * HDIM;
            const uint32_t sbase = sb + FKVOFF + (uint32_t)st * FSTAGE;
            #pragma unroll
            for (int pp = 0; pp < 4; ++pp) {
                #pragma unroll
                for (int t = 0; t < 2; ++t) {
                    int idx = tid + t * 256;
                    int r = idx >> 3, c = (idx & 7) * 8;
                    cp_async16(sbase + (uint32_t)pp * FARR + (uint32_t)(r * FSTR + c) * 2,
                               kv_src[pp] + gb + (size_t)r * D_MODEL + c);
                }
            }
            asm volatile("cp.async.commit_group;" ::: "memory");
        };

        const int jend = 4 * bx + 4;
        load_kv(0, 0);
        if (jend > 1) load_kv(1, 1);

        float o[2][8][4] = {};
        float mrow[2][2] = {{-1e30f, -1e30f}, {-1e30f, -1e30f}};
        float lrow[2][2] = {};

        for (int j = 0; j < jend; ++j) {
            if (j + 1 < jend) {
                asm volatile("cp.async.wait_group 1;" ::: "memory");
            } else {
                asm volatile("cp.async.wait_group 0;" ::: "memory");
            }
            __syncthreads();
            if (j + 2 < jend) load_kv(j + 2, (j + 2) % 3);

            const int k0 = j * 64;
            if (k0 <= q0 + w * 32 + 31) {
                const uint32_t sbase = sb + FKVOFF + (uint32_t)(j % 3) * FSTAGE;

                float sreg[2][8][4] = {};
                #pragma unroll
                for (int ks = 0; ks < 4; ++ks) {
                    uint32_t bh[8][2], bl[8][2];
                    #pragma unroll
                    for (int g = 0; g < 4; ++g) {
                        const int row = g * 16 + (lane >> 4) * 8 + (lane & 7);
                        const int col = ks * 16 + ((lane >> 3) & 1) * 8;
                        uint32_t addr = sbase + (uint32_t)(row * FSTR + col) * 2;
                        uint32_t r4[4];
                        ldmx4(r4, addr);
                        bh[2*g][0]=r4[0]; bh[2*g][1]=r4[1]; bh[2*g+1][0]=r4[2]; bh[2*g+1][1]=r4[3];
                        ldmx4(r4, addr + FARR);
                        bl[2*g][0]=r4[0]; bl[2*g][1]=r4[1]; bl[2*g+1][0]=r4[2]; bl[2*g+1][1]=r4[3];
                    }
                    #pragma unroll
                    for (int mf = 0; mf < 2; ++mf) {
                        const int qrow = w * 32 + mf * 16 + (lane & 15);
                        const int qcol = ks * 16 + (lane >> 4) * 8;
                        uint32_t qaddr = sb + (uint32_t)(qrow * FSTR + qcol) * 2;
                        uint32_t qhf[4], qlf[4];
                        ldmx4(qhf, qaddr);
                        ldmx4(qlf, qaddr + FQARR);
                        #pragma unroll
                        for (int n = 0; n < 8; ++n) mma16816(sreg[mf][n], qhf, bh[n]);
                        #pragma unroll
                        for (int n = 0; n < 8; ++n) mma16816(sreg[mf][n], qhf, bl[n]);
                        #pragma unroll
                        for (int n = 0; n < 8; ++n) mma16816(sreg[mf][n], qlf, bh[n]);
                    }
                }

                uint32_t ph[2][2][8];
                float a[2][2];
                #pragma unroll
                for (int mf = 0; mf < 2; ++mf) {
                    const int gr = q0 + w * 32 + mf * 16 + (lane >> 2);
                    if (k0 + 63 > q0 + w * 32 + mf * 16) {
                        #pragma unroll
                        for (int t = 0; t < 8; ++t) {
                            int c = k0 + t * 8 + 2 * (lane & 3);
                            if (c     > gr)     sreg[mf][t][0] = -1e30f;
                            if (c + 1 > gr)     sreg[mf][t][1] = -1e30f;
                            if (c     > gr + 8) sreg[mf][t][2] = -1e30f;
                            if (c + 1 > gr + 8) sreg[mf][t][3] = -1e30f;
                        }
                    }
                    float mx0 = -1e30f, mx1 = -1e30f;
                    #pragma unroll
                    for (int t = 0; t < 8; ++t) {
                        mx0 = fmaxf(mx0, fmaxf(sreg[mf][t][0], sreg[mf][t][1]));
                        mx1 = fmaxf(mx1, fmaxf(sreg[mf][t][2], sreg[mf][t][3]));
                    }
                    mx0 = fmaxf(mx0, __shfl_xor_sync(0xffffffffu, mx0, 1));
                    mx0 = fmaxf(mx0, __shfl_xor_sync(0xffffffffu, mx0, 2));
                    mx1 = fmaxf(mx1, __shfl_xor_sync(0xffffffffu, mx1, 1));
                    mx1 = fmaxf(mx1, __shfl_xor_sync(0xffffffffu, mx1, 2));
                    const float mn0 = fmaxf(mrow[mf][0], mx0), mn1 = fmaxf(mrow[mf][1], mx1);
                    a[mf][0] = __expf(mrow[mf][0] - mn0);
                    a[mf][1] = __expf(mrow[mf][1] - mn1);
                    mrow[mf][0] = mn0; mrow[mf][1] = mn1;

                    float ps0 = 0.0f, ps1 = 0.0f;
                    #pragma unroll
                    for (int t = 0; t < 8; ++t) {
                        float p0 = __expf(sreg[mf][t][0] - mn0), p1 = __expf(sreg[mf][t][1] - mn0);
                        float p2 = __expf(sreg[mf][t][2] - mn1), p3 = __expf(sreg[mf][t][3] - mn1);
                        ps0 += p0 + p1; ps1 += p2 + p3;
                        __half2 h01 = __floats2half2_rn(p0, p1);
                        __half2 h23 = __floats2half2_rn(p2, p3);
                        ph[mf][0][t] = *(uint32_t*)&h01;
                        ph[mf][1][t] = *(uint32_t*)&h23;
                    }
                    ps0 += __shfl_xor_sync(0xffffffffu, ps0, 1);
                    ps0 += __shfl_xor_sync(0xffffffffu, ps0, 2);
                    ps1 += __shfl_xor_sync(0xffffffffu, ps1, 1);
                    ps1 += __shfl_xor_sync(0xffffffffu, ps1, 2);
                    lrow[mf][0] = lrow[mf][0] * a[mf][0] + ps0;
                    lrow[mf][1] = lrow[mf][1] * a[mf][1] + ps1;

                    #pragma unroll
                    for (int t = 0; t < 8; ++t) {
                        o[mf][t][0] *= a[mf][0]; o[mf][t][1] *= a[mf][0];
                        o[mf][t][2] *= a[mf][1]; o[mf][t][3] *= a[mf][1];
                    }
                }

                #pragma unroll
                for (int ks = 0; ks < 4; ++ks) {
                    uint32_t bvh[8][2], bvl[8][2];
                    #pragma unroll
                    for (int g = 0; g < 4; ++g) {
                        const int row = ks * 16 + (lane & 15);
                        const int col = g * 16 + (lane >> 4) * 8;
                        uint32_t addr = sbase + 2u * FARR + (uint32_t)(row * FSTR + col) * 2;
                        uint32_t r4[4];
                        ldmx4t(r4, addr);
                        bvh[2*g][0]=r4[0]; bvh[2*g][1]=r4[1]; bvh[2*g+1][0]=r4[2]; bvh[2*g+1][1]=r4[3];
                        ldmx4t(r4, addr + FARR);
                        bvl[2*g][0]=r4[0]; bvl[2*g][1]=r4[1]; bvl[2*g+1][0]=r4[2]; bvl[2*g+1][1]=r4[3];
                    }
                    #pragma unroll
                    for (int mf = 0; mf < 2; ++mf) {
                        uint32_t pah[4] = {ph[mf][0][2*ks], ph[mf][1][2*ks],
                                           ph[mf][0][2*ks+1], ph[mf][1][2*ks+1]};
                        #pragma unroll
                        for (int n = 0; n < 8; ++n) mma16816(o[mf][n], pah, bvh[n]);
                        #pragma unroll
                        for (int n = 0; n < 8; ++n) mma16816(o[mf][n], pah, bvl[n]);
                    }
                }
            }
        }

        const size_t ob = (size_t)b * S_LEN * D_MODEL + h * HDIM;
        #pragma unroll
        for (int mf = 0; mf < 2; ++mf) {
            const float inv0 = 1.0f / lrow[mf][0], inv1 = 1.0f / lrow[mf][1];
            const int gr = q0 + w * 32 + mf * 16 + (lane >> 2);
            #pragma unroll
            for (int t = 0; t < 8; ++t) {
                const int c = t * 8 + 2 * (lane & 3);
                __half2 v0 = __floats2half2_rn(o[mf][t][0] * inv0, o[mf][t][1] * inv0);
                __half2 v1 = __floats2half2_rn(o[mf][t][2] * inv1, o[mf][t][3] * inv1);
                *(__half2*)(AOh + ob + (size_t)gr * D_MODEL + c)       = v0;
                *(__half2*)(AOh + ob + (size_t)(gr + 8) * D_MODEL + c) = v1;
            }
        }
    }
}

// ---------------------------------------------------------------------------
extern "C" void kernel_launch(void* const* d_in, const int* in_sizes, int n_in,
                              void* d_out, int out_size)
{
    const float* x  = (const float*)d_in[0];
    const float* qw = (const float*)d_in[1];
    const float* kw = (const float*)d_in[2];
    const float* vw = (const float*)d_in[3];
    const float* ow = (const float*)d_in[4];

    const int M = in_sizes[0] / D_MODEL;
    const int B = M / S_LEN;
    const int W = D_MODEL * D_MODEL;

    void *pxh, *pxl, *pah, *pwh, *pwl;
    void *pqh, *pql, *pkh, *pkl, *pvh, *pvl, *pct, *pst;
    cudaGetSymbolAddress(&pxh, g_xh);  cudaGetSymbolAddress(&pxl, g_xl);
    cudaGetSymbolAddress(&pah, g_aoh);
    cudaGetSymbolAddress(&pwh, g_wh);  cudaGetSymbolAddress(&pwl, g_wl);
    cudaGetSymbolAddress(&pqh, g_qh);  cudaGetSymbolAddress(&pql, g_ql);
    cudaGetSymbolAddress(&pkh, g_kh);  cudaGetSymbolAddress(&pkl, g_kl);
    cudaGetSymbolAddress(&pvh, g_vh);  cudaGetSymbolAddress(&pvl, g_vl);
    cudaGetSymbolAddress(&pct, g_ct);  cudaGetSymbolAddress(&pst, g_st);
    __half* xh = (__half*)pxh;  __half* xl = (__half*)pxl;
    __half* aoh = (__half*)pah;
    __half* wh = (__half*)pwh;  __half* wl = (__half*)pwl;
    __half* qhp = (__half*)pqh; __half* qlp = (__half*)pql;
    __half* khp = (__half*)pkh; __half* klp = (__half*)pkl;
    __half* vhp = (__half*)pvh; __half* vlp = (__half*)pvl;
    float* ct = (float*)pct; float* st = (float*)pst;

    int n4x = M * D_MODEL / 4;
    split_kernel<<<(n4x + 255) / 256, 256>>>(x, xh, xl, n4x);
    int n4w = W / 4;
    dim3 wgrid((n4w + 255) / 256, 4);
    split_w4<<<wgrid, 256>>>(qw, kw, vw, ow, wh, wl, n4w);
    rope_tab<<<(S_LEN * 32 + 255) / 256, 256>>>(ct, st);

    cudaFuncSetAttribute(gemm_qkv, cudaFuncAttributeMaxDynamicSharedMemorySize, G_SMEM_SZ);
    dim3 qkvgrid(D_MODEL / 128, M / 128, 3);
    gemm_qkv<<<qkvgrid, 256, G_SMEM_SZ>>>(xh, xl, wh, wl,
                                          qhp, qlp, khp, klp, vhp, vlp,
                                          ct, st, M, D_MODEL, D_MODEL);

    cudaFuncSetAttribute(flash_mma, cudaFuncAttributeMaxDynamicSharedMemorySize, F_SMEM);
    const int NB = NHEAD * B;
    flash_mma<<<2 * NB, 256, F_SMEM>>>(qhp, qlp, khp, klp, vhp, vlp, aoh, NB);

    cudaFuncSetAttribute(gemm_mma, cudaFuncAttributeMaxDynamicSharedMemorySize, G_SMEM_SZ);
    dim3 ggrid(D_MODEL / 128, M / 128);
    gemm_mma<<<ggrid, 256, G_SMEM_SZ>>>(aoh, wh + 3 * W, wl + 3 * W,
                                        (float*)d_out, M, D_MODEL, D_MODEL);
}

// round 17
// speedup vs baseline: 1.2586x; 1.0779x over previous
#include <cuda_runtime.h>
#include <cuda_fp16.h>
#include <math.h>
#include <stdint.h>

#define D_MODEL 1024
#define S_LEN   2048
#define NHEAD   16
#define HDIM    64
#define MAXB    4
#define MMAX    (MAXB * S_LEN)

// ---------------- scratch (__device__ globals; no allocs allowed) ----------
__device__ __half g_xh [MMAX * D_MODEL];
__device__ __half g_xl [MMAX * D_MODEL];
__device__ __half g_aoh[MMAX * D_MODEL];
__device__ __half g_wh [4 * D_MODEL * D_MODEL];
__device__ __half g_wl [4 * D_MODEL * D_MODEL];
__device__ __half g_qh [MMAX * D_MODEL];
__device__ __half g_ql [MMAX * D_MODEL];
__device__ __half g_kh [MMAX * D_MODEL];
__device__ __half g_kl [MMAX * D_MODEL];
__device__ __half g_vh [MMAX * D_MODEL];
__device__ float g_ct[S_LEN * 32];
__device__ float g_st[S_LEN * 32];

// ---------------- helpers ----------------------------------------------------
__device__ __forceinline__ uint32_t smem_u32(const void* p) {
    uint32_t a;
    asm("{ .reg .u64 t; cvta.to.shared.u64 t, %1; cvt.u32.u64 %0, t; }" : "=r"(a) : "l"(p));
    return a;
}
__device__ __forceinline__ void cp_async16(uint32_t saddr, const void* gptr) {
    asm volatile("cp.async.cg.shared.global [%0], [%1], 16;" :: "r"(saddr), "l"(gptr));
}
__device__ __forceinline__ void ldmx4(uint32_t* r, uint32_t addr) {
    asm volatile("ldmatrix.sync.aligned.m8n8.x4.shared.b16 {%0,%1,%2,%3}, [%4];"
                 : "=r"(r[0]), "=r"(r[1]), "=r"(r[2]), "=r"(r[3]) : "r"(addr));
}
__device__ __forceinline__ void ldmx4t(uint32_t* r, uint32_t addr) {
    asm volatile("ldmatrix.sync.aligned.m8n8.x4.trans.shared.b16 {%0,%1,%2,%3}, [%4];"
                 : "=r"(r[0]), "=r"(r[1]), "=r"(r[2]), "=r"(r[3]) : "r"(addr));
}
__device__ __forceinline__ void mma16816(float* d, const uint32_t* a, const uint32_t* b) {
    asm volatile("mma.sync.aligned.m16n8k16.row.col.f32.f16.f16.f32 "
                 "{%0,%1,%2,%3}, {%4,%5,%6,%7}, {%8,%9}, {%0,%1,%2,%3};"
                 : "+f"(d[0]), "+f"(d[1]), "+f"(d[2]), "+f"(d[3])
                 : "r"(a[0]), "r"(a[1]), "r"(a[2]), "r"(a[3]), "r"(b[0]), "r"(b[1]));
}
__device__ __forceinline__ void store_split_pair(
    __half* H, __half* L, size_t off, float a, float b)
{
    __half2 hi = __floats2half2_rn(a, b);
    __half2 lo = __floats2half2_rn(a - __half2float(hi.x), b - __half2float(hi.y));
    *(__half2*)(H + off) = hi;
    *(__half2*)(L + off) = lo;
}

// ---------------- split fp32 -> fp16 hi/lo ----------------------------------
__global__ void split_kernel(const float* __restrict__ X,
                             __half* __restrict__ H,
                             __half* __restrict__ L, int n4)
{
    int i = blockIdx.x * blockDim.x + threadIdx.x;
    if (i >= n4) return;
    float4 v = ((const float4*)X)[i];
    __half2 hA = __floats2half2_rn(v.x, v.y);
    __half2 hB = __floats2half2_rn(v.z, v.w);
    __half2 lA = __floats2half2_rn(v.x - __half2float(hA.x), v.y - __half2float(hA.y));
    __half2 lB = __floats2half2_rn(v.z - __half2float(hB.x), v.w - __half2float(hB.y));
    uint2 hv, lv;
    hv.x = *(uint32_t*)&hA; hv.y = *(uint32_t*)&hB;
    lv.x = *(uint32_t*)&lA; lv.y = *(uint32_t*)&lB;
    ((uint2*)H)[i] = hv;
    ((uint2*)L)[i] = lv;
}

__global__ void split_w4(const float* __restrict__ W0, const float* __restrict__ W1,
                         const float* __restrict__ W2, const float* __restrict__ W3,
                         __half* __restrict__ H, __half* __restrict__ L, int n4)
{
    int i = blockIdx.x * blockDim.x + threadIdx.x;
    if (i >= n4) return;
    int z = blockIdx.y;
    const float* X = (z == 0) ? W0 : (z == 1) ? W1 : (z == 2) ? W2 : W3;
    float4 v = ((const float4*)X)[i];
    __half2 hA = __floats2half2_rn(v.x, v.y);
    __half2 hB = __floats2half2_rn(v.z, v.w);
    __half2 lA = __floats2half2_rn(v.x - __half2float(hA.x), v.y - __half2float(hA.y));
    __half2 lB = __floats2half2_rn(v.z - __half2float(hB.x), v.w - __half2float(hB.y));
    uint2 hv, lv;
    hv.x = *(uint32_t*)&hA; hv.y = *(uint32_t*)&hB;
    lv.x = *(uint32_t*)&lA; lv.y = *(uint32_t*)&lB;
    ((uint2*)(H + (size_t)z * D_MODEL * D_MODEL))[i] = hv;
    ((uint2*)(L + (size_t)z * D_MODEL * D_MODEL))[i] = lv;
}

// ---------------- RoPE cos/sin table ----------------------------------------
__global__ void rope_tab(float* __restrict__ ct, float* __restrict__ st)
{
    int idx = blockIdx.x * blockDim.x + threadIdx.x;
    if (idx >= S_LEN * 32) return;
    int s = idx >> 5, i = idx & 31;
    float inv = expf(-logf(10000.0f) * ((float)i / 32.0f));
    float sn, cs;
    sincosf((float)s * inv, &sn, &cs);
    ct[idx] = cs; st[idx] = sn;
}

// ---------------- GEMM core: 128x128, 2-stage ring ---------------------------
// slots: 0 = A-hi, 1 = A-lo (3-term), 2 = B-hi, 3 = B-lo (>=2-term)
#define GSTRIDE 40
#define GARR    (128 * GSTRIDE * 2)      // 10240 B
#define GBUF    (4 * GARR)               // 40960 B per stage
#define G_SMEM_SZ (2 * GBUF)             // 81920 B -> 2 CTAs/SM

__device__ __forceinline__ void gemm_chunk_compute(
    uint32_t boff, int lane, int warp_m, int warp_n, float acc[4][4][4], int nterms)
{
    const int arow = warp_m * 64 + (lane & 15);
    const int brow_base = warp_n * 32 + ((lane >> 4) * 8) + (lane & 7);
    #pragma unroll
    for (int ks = 0; ks < 2; ++ks) {
        const int acol = ks * 16 + (lane >> 4) * 8;
        const int bcol = ks * 16 + ((lane >> 3) & 1) * 8;
        uint32_t bh[4][2], bl[4][2];
        #pragma unroll
        for (int g = 0; g < 2; ++g) {
            uint32_t addr = boff + 2 * GARR +
                            (uint32_t)((brow_base + g * 16) * GSTRIDE + bcol) * 2;
            uint32_t r[4];
            ldmx4(r, addr);
            bh[2*g][0] = r[0]; bh[2*g][1] = r[1];
            bh[2*g+1][0] = r[2]; bh[2*g+1][1] = r[3];
            if (nterms >= 2) {
                ldmx4(r, addr + GARR);
                bl[2*g][0] = r[0]; bl[2*g][1] = r[1];
                bl[2*g+1][0] = r[2]; bl[2*g+1][1] = r[3];
            }
        }
        #pragma unroll
        for (int half = 0; half < 2; ++half) {
            uint32_t ah[2][4], al[2][4];
            #pragma unroll
            for (int mi = 0; mi < 2; ++mi) {
                uint32_t addr = boff +
                    (uint32_t)((arow + (half * 2 + mi) * 16) * GSTRIDE + acol) * 2;
                ldmx4(ah[mi], addr);
                if (nterms >= 3) ldmx4(al[mi], addr + GARR);
            }
            #pragma unroll
            for (int mi = 0; mi < 2; ++mi)
                #pragma unroll
                for (int ni = 0; ni < 4; ++ni) {
                    float* a = acc[half * 2 + mi][ni];
                    mma16816(a, ah[mi], bh[ni]);
                    if (nterms >= 2) mma16816(a, ah[mi], bl[ni]);
                    if (nterms >= 3) mma16816(a, al[mi], bh[ni]);
                }
        }
    }
}

// ---------------- fused QKV mega-GEMM (Q/K 3-term, V 1-term) -----------------
__global__ __launch_bounds__(256, 2) void gemm_qkv(
    const __half* __restrict__ Ah, const __half* __restrict__ Al,
    const __half* __restrict__ Wh, const __half* __restrict__ Wl,
    __half* __restrict__ Qh, __half* __restrict__ Ql,
    __half* __restrict__ Kh, __half* __restrict__ Kl,
    __half* __restrict__ Vh,
    const float* __restrict__ ct, const float* __restrict__ st,
    int M, int N, int K)
{
    extern __shared__ char smem[];
    const uint32_t sb = smem_u32(smem);
    const int tid = threadIdx.x;
    const int lane = tid & 31;
    const int wid = tid >> 5;
    const int warp_m = wid >> 2;
    const int warp_n = wid & 3;
    const int m0 = blockIdx.y * 128, n0 = blockIdx.x * 128;
    const int z = blockIdx.z;
    const int nterms = (z < 2) ? 3 : 1;

    const __half* Bh = Wh + (size_t)z * K * N;
    const __half* Bl = Wl + (size_t)z * K * N;

    float acc[4][4][4] = {};
    const __half* srcs[4] = {Ah, Al, Bh, Bl};

    auto load_chunk = [&](int k0, int buf) {
        const uint32_t boff = sb + (uint32_t)buf * GBUF;
        #pragma unroll
        for (int p = 0; p < 4; ++p) {
            if (p == 1 && nterms < 3) continue;   // A-lo only for 3-term
            if (p == 3 && nterms < 2) continue;   // B-lo only for >=2-term
            const __half* src = srcs[p];
            const int r0 = (p < 2) ? m0 : n0;
            const uint32_t abase = boff + (uint32_t)p * GARR;
            #pragma unroll
            for (int t = 0; t < 2; ++t) {
                int u = tid + t * 256;
                int row = u >> 2, c = (u & 3) * 8;
                cp_async16(abase + (uint32_t)(row * GSTRIDE + c) * 2,
                           src + (size_t)(r0 + row) * K + k0 + c);
            }
        }
        asm volatile("cp.async.commit_group;" ::: "memory");
    };

    load_chunk(0, 0);

    const int nch = K / 32;
    for (int c = 0; c < nch; ++c) {
        asm volatile("cp.async.wait_group 0;" ::: "memory");
        __syncthreads();
        if (c + 1 < nch) load_chunk((c + 1) * 32, (c + 1) & 1);
        gemm_chunk_compute(sb + (uint32_t)(c & 1) * GBUF, lane, warp_m, warp_n, acc, nterms);
    }

    const float qscale = (z == 0) ? 0.125f : 1.0f;

    #pragma unroll
    for (int mi = 0; mi < 4; ++mi) {
        const int r = m0 + warp_m * 64 + mi * 16 + (lane >> 2);
        const int s0 = r & (S_LEN - 1);
        const int s1 = (r + 8) & (S_LEN - 1);
        #pragma unroll
        for (int ni = 0; ni < 4; ++ni) {
            const int cidx = n0 + warp_n * 32 + ni * 8 + (lane & 3) * 2;
            float a0 = acc[mi][ni][0], a1 = acc[mi][ni][1];
            float b0 = acc[mi][ni][2], b1 = acc[mi][ni][3];
            if (z < 2) {
                const int i = (cidx & (HDIM - 1)) >> 1;
                float c0 = ct[s0 * 32 + i], sn0 = st[s0 * 32 + i];
                float c1 = ct[s1 * 32 + i], sn1 = st[s1 * 32 + i];
                float e = a0, o = a1;
                a0 = (e * c0 - o * sn0) * qscale;
                a1 = (e * sn0 + o * c0) * qscale;
                e = b0; o = b1;
                b0 = (e * c1 - o * sn1) * qscale;
                b1 = (e * sn1 + o * c1) * qscale;
                __half* H = (z == 0) ? Qh : Kh;
                __half* L = (z == 0) ? Ql : Kl;
                store_split_pair(H, L, (size_t)r * N + cidx, a0, a1);
                store_split_pair(H, L, (size_t)(r + 8) * N + cidx, b0, b1);
            } else {
                __half2 v0 = __floats2half2_rn(a0, a1);
                __half2 v1 = __floats2half2_rn(b0, b1);
                *(__half2*)(Vh + (size_t)r * N + cidx)       = v0;
                *(__half2*)(Vh + (size_t)(r + 8) * N + cidx) = v1;
            }
        }
    }
}

// ---------------- plain GEMM (final O-proj, 2-term) ---------------------------
__global__ __launch_bounds__(256, 2) void gemm_mma(
    const __half* __restrict__ Ah,
    const __half* __restrict__ Bh, const __half* __restrict__ Bl,
    float* __restrict__ C, int M, int N, int K)
{
    extern __shared__ char smem[];
    const uint32_t sb = smem_u32(smem);
    const int tid = threadIdx.x;
    const int lane = tid & 31;
    const int wid = tid >> 5;
    const int warp_m = wid >> 2;
    const int warp_n = wid & 3;
    const int m0 = blockIdx.y * 128, n0 = blockIdx.x * 128;

    float acc[4][4][4] = {};
    const __half* srcs[3] = {Ah, Bh, Bl};
    const uint32_t slot[3] = {0, 2, 3};

    auto load_chunk = [&](int k0, int buf) {
        const uint32_t boff = sb + (uint32_t)buf * GBUF;
        #pragma unroll
        for (int p = 0; p < 3; ++p) {
            const __half* src = srcs[p];
            const int r0 = (p == 0) ? m0 : n0;
            const uint32_t abase = boff + slot[p] * GARR;
            #pragma unroll
            for (int t = 0; t < 2; ++t) {
                int u = tid + t * 256;
                int row = u >> 2, c = (u & 3) * 8;
                cp_async16(abase + (uint32_t)(row * GSTRIDE + c) * 2,
                           src + (size_t)(r0 + row) * K + k0 + c);
            }
        }
        asm volatile("cp.async.commit_group;" ::: "memory");
    };

    load_chunk(0, 0);

    const int nch = K / 32;
    for (int c = 0; c < nch; ++c) {
        asm volatile("cp.async.wait_group 0;" ::: "memory");
        __syncthreads();
        if (c + 1 < nch) load_chunk((c + 1) * 32, (c + 1) & 1);
        gemm_chunk_compute(sb + (uint32_t)(c & 1) * GBUF, lane, warp_m, warp_n, acc, 2);
    }

    #pragma unroll
    for (int mi = 0; mi < 4; ++mi) {
        const int r = m0 + warp_m * 64 + mi * 16 + (lane >> 2);
        #pragma unroll
        for (int ni = 0; ni < 4; ++ni) {
            const int cidx = n0 + warp_n * 32 + ni * 8 + (lane & 3) * 2;
            float2 v0 = {acc[mi][ni][0], acc[mi][ni][1]};
            float2 v1 = {acc[mi][ni][2], acc[mi][ni][3]};
            *(float2*)(C + (size_t)r * N + cidx)       = v0;
            *(float2*)(C + (size_t)(r + 8) * N + cidx) = v1;
        }
    }
}

// ---------------- persistent, statically-balanced causal flash --------------
// KV stage = Kh, Kl, Vh (3 arrays). PV single-term.
#define FSTR   72
#define FARR   (64 * FSTR * 2)          // 9216 B
#define FSTAGE (3 * FARR)               // 27648 B (Kh,Kl,Vh)
#define FQARR  (256 * FSTR * 2)         // 36864 B
#define FKVOFF (2 * FQARR)              // 73728
#define F_SMEM (FKVOFF + 3 * FSTAGE)    // 156672 B

__global__ __launch_bounds__(256, 1) void flash_mma(
    const __half* __restrict__ Qh_, const __half* __restrict__ Ql_,
    const __half* __restrict__ Kh_, const __half* __restrict__ Kl_,
    const __half* __restrict__ Vh_,
    __half* __restrict__ AOh, int NB)
{
    extern __shared__ char smem[];
    const uint32_t sb = smem_u32(smem);
    const int tid = threadIdx.x, lane = tid & 31, w = tid >> 5;
    const int p = blockIdx.x;

    const __half* kv_src[3] = {Kh_, Kl_, Vh_};

    #pragma unroll 1
    for (int pass = 0; pass < 4; ++pass) {
        int s;
        switch (pass) {
            case 0:  s = p;              break;
            case 1:  s = 4 * NB - 1 - p; break;
            case 2:  s = 4 * NB + p;     break;
            default: s = 8 * NB - 1 - p; break;
        }
        const int bx = s / NB;
        const int r_ = s % NB;
        const int h = r_ & (NHEAD - 1);
        const int b = r_ >> 4;
        const int q0 = bx * 256;

        __syncthreads();

        const size_t base_q = (size_t)(b * S_LEN + q0) * D_MODEL + h * HDIM;
        #pragma unroll
        for (int t = 0; t < 8; ++t) {
            int idx = tid + t * 256;
            int r = idx >> 3, c = (idx & 7) * 8;
            cp_async16(sb + (uint32_t)(r * FSTR + c) * 2,
                       Qh_ + base_q + (size_t)r * D_MODEL + c);
            cp_async16(sb + FQARR + (uint32_t)(r * FSTR + c) * 2,
                       Ql_ + base_q + (size_t)r * D_MODEL + c);
        }
        asm volatile("cp.async.commit_group;" ::: "memory");

        auto load_kv = [&](int j, int st) {
            const size_t gb = (size_t)(b * S_LEN + j * 64) * D_MODEL + h * HDIM;
            const uint32_t sbase = sb + FKVOFF + (uint32_t)st * FSTAGE;
            #pragma unroll
            for (int pp = 0; pp < 3; ++pp) {
                #pragma unroll
                for (int t = 0; t < 2; ++t) {
                    int idx = tid + t * 256;
                    int r = idx >> 3, c = (idx & 7) * 8;
                    cp_async16(sbase + (uint32_t)pp * FARR + (uint32_t)(r * FSTR + c) * 2,
                               kv_src[pp] + gb + (size_t)r * D_MODEL + c);
                }
            }
            asm volatile("cp.async.commit_group;" ::: "memory");
        };

        const int jend = 4 * bx + 4;
        load_kv(0, 0);
        if (jend > 1) load_kv(1, 1);

        float o[2][8][4] = {};
        float mrow[2][2] = {{-1e30f, -1e30f}, {-1e30f, -1e30f}};
        float lrow[2][2] = {};

        for (int j = 0; j < jend; ++j) {
            if (j + 1 < jend) {
                asm volatile("cp.async.wait_group 1;" ::: "memory");
            } else {
                asm volatile("cp.async.wait_group 0;" ::: "memory");
            }
            __syncthreads();
            if (j + 2 < jend) load_kv(j + 2, (j + 2) % 3);

            const int k0 = j * 64;
            if (k0 <= q0 + w * 32 + 31) {
                const uint32_t sbase = sb + FKVOFF + (uint32_t)(j % 3) * FSTAGE;

                float sreg[2][8][4] = {};
                #pragma unroll
                for (int ks = 0; ks < 4; ++ks) {
                    uint32_t bh[8][2], bl[8][2];
                    #pragma unroll
                    for (int g = 0; g < 4; ++g) {
                        const int row = g * 16 + (lane >> 4) * 8 + (lane & 7);
                        const int col = ks * 16 + ((lane >> 3) & 1) * 8;
                        uint32_t addr = sbase + (uint32_t)(row * FSTR + col) * 2;
                        uint32_t r4[4];
                        ldmx4(r4, addr);
                        bh[2*g][0]=r4[0]; bh[2*g][1]=r4[1]; bh[2*g+1][0]=r4[2]; bh[2*g+1][1]=r4[3];
                        ldmx4(r4, addr + FARR);
                        bl[2*g][0]=r4[0]; bl[2*g][1]=r4[1]; bl[2*g+1][0]=r4[2]; bl[2*g+1][1]=r4[3];
                    }
                    #pragma unroll
                    for (int mf = 0; mf < 2; ++mf) {
                        const int qrow = w * 32 + mf * 16 + (lane & 15);
                        const int qcol = ks * 16 + (lane >> 4) * 8;
                        uint32_t qaddr = sb + (uint32_t)(qrow * FSTR + qcol) * 2;
                        uint32_t qhf[4], qlf[4];
                        ldmx4(qhf, qaddr);
                        ldmx4(qlf, qaddr + FQARR);
                        #pragma unroll
                        for (int n = 0; n < 8; ++n) mma16816(sreg[mf][n], qhf, bh[n]);
                        #pragma unroll
                        for (int n = 0; n < 8; ++n) mma16816(sreg[mf][n], qhf, bl[n]);
                        #pragma unroll
                        for (int n = 0; n < 8; ++n) mma16816(sreg[mf][n], qlf, bh[n]);
                    }
                }

                uint32_t ph[2][2][8];
                float a[2][2];
                #pragma unroll
                for (int mf = 0; mf < 2; ++mf) {
                    const int gr = q0 + w * 32 + mf * 16 + (lane >> 2);
                    if (k0 + 63 > q0 + w * 32 + mf * 16) {
                        #pragma unroll
                        for (int t = 0; t < 8; ++t) {
                            int c = k0 + t * 8 + 2 * (lane & 3);
                            if (c     > gr)     sreg[mf][t][0] = -1e30f;
                            if (c + 1 > gr)     sreg[mf][t][1] = -1e30f;
                            if (c     > gr + 8) sreg[mf][t][2] = -1e30f;
                            if (c + 1 > gr + 8) sreg[mf][t][3] = -1e30f;
                        }
                    }
                    float mx0 = -1e30f, mx1 = -1e30f;
                    #pragma unroll
                    for (int t = 0; t < 8; ++t) {
                        mx0 = fmaxf(mx0, fmaxf(sreg[mf][t][0], sreg[mf][t][1]));
                        mx1 = fmaxf(mx1, fmaxf(sreg[mf][t][2], sreg[mf][t][3]));
                    }
                    mx0 = fmaxf(mx0, __shfl_xor_sync(0xffffffffu, mx0, 1));
                    mx0 = fmaxf(mx0, __shfl_xor_sync(0xffffffffu, mx0, 2));
                    mx1 = fmaxf(mx1, __shfl_xor_sync(0xffffffffu, mx1, 1));
                    mx1 = fmaxf(mx1, __shfl_xor_sync(0xffffffffu, mx1, 2));
                    const float mn0 = fmaxf(mrow[mf][0], mx0), mn1 = fmaxf(mrow[mf][1], mx1);
                    a[mf][0] = __expf(mrow[mf][0] - mn0);
                    a[mf][1] = __expf(mrow[mf][1] - mn1);
                    mrow[mf][0] = mn0; mrow[mf][1] = mn1;

                    float ps0 = 0.0f, ps1 = 0.0f;
                    #pragma unroll
                    for (int t = 0; t < 8; ++t) {
                        float p0 = __expf(sreg[mf][t][0] - mn0), p1 = __expf(sreg[mf][t][1] - mn0);
                        float p2 = __expf(sreg[mf][t][2] - mn1), p3 = __expf(sreg[mf][t][3] - mn1);
                        ps0 += p0 + p1; ps1 += p2 + p3;
                        __half2 h01 = __floats2half2_rn(p0, p1);
                        __half2 h23 = __floats2half2_rn(p2, p3);
                        ph[mf][0][t] = *(uint32_t*)&h01;
                        ph[mf][1][t] = *(uint32_t*)&h23;
                    }
                    ps0 += __shfl_xor_sync(0xffffffffu, ps0, 1);
                    ps0 += __shfl_xor_sync(0xffffffffu, ps0, 2);
                    ps1 += __shfl_xor_sync(0xffffffffu, ps1, 1);
                    ps1 += __shfl_xor_sync(0xffffffffu, ps1, 2);
                    lrow[mf][0] = lrow[mf][0] * a[mf][0] + ps0;
                    lrow[mf][1] = lrow[mf][1] * a[mf][1] + ps1;

                    #pragma unroll
                    for (int t = 0; t < 8; ++t) {
                        o[mf][t][0] *= a[mf][0]; o[mf][t][1] *= a[mf][0];
                        o[mf][t][2] *= a[mf][1]; o[mf][t][3] *= a[mf][1];
                    }
                }

                // ---- O += Ph @ Vh (single term; V is plain fp16)
                #pragma unroll
                for (int ks = 0; ks < 4; ++ks) {
                    uint32_t bvh[8][2];
                    #pragma unroll
                    for (int g = 0; g < 4; ++g) {
                        const int row = ks * 16 + (lane & 15);
                        const int col = g * 16 + (lane >> 4) * 8;
                        uint32_t addr = sbase + 2u * FARR + (uint32_t)(row * FSTR + col) * 2;
                        uint32_t r4[4];
                        ldmx4t(r4, addr);
                        bvh[2*g][0]=r4[0]; bvh[2*g][1]=r4[1]; bvh[2*g+1][0]=r4[2]; bvh[2*g+1][1]=r4[3];
                    }
                    #pragma unroll
                    for (int mf = 0; mf < 2; ++mf) {
                        uint32_t pah[4] = {ph[mf][0][2*ks], ph[mf][1][2*ks],
                                           ph[mf][0][2*ks+1], ph[mf][1][2*ks+1]};
                        #pragma unroll
                        for (int n = 0; n < 8; ++n) mma16816(o[mf][n], pah, bvh[n]);
                    }
                }
            }
        }

        const size_t ob = (size_t)b * S_LEN * D_MODEL + h * HDIM;
        #pragma unroll
        for (int mf = 0; mf < 2; ++mf) {
            const float inv0 = 1.0f / lrow[mf][0], inv1 = 1.0f / lrow[mf][1];
            const int gr = q0 + w * 32 + mf * 16 + (lane >> 2);
            #pragma unroll
            for (int t = 0; t < 8; ++t) {
                const int c = t * 8 + 2 * (lane & 3);
                __half2 v0 = __floats2half2_rn(o[mf][t][0] * inv0, o[mf][t][1] * inv0);
                __half2 v1 = __floats2half2_rn(o[mf][t][2] * inv1, o[mf][t][3] * inv1);
                *(__half2*)(AOh + ob + (size_t)gr * D_MODEL + c)       = v0;
                *(__half2*)(AOh + ob + (size_t)(gr + 8) * D_MODEL + c) = v1;
            }
        }
    }
}

// ---------------------------------------------------------------------------
extern "C" void kernel_launch(void* const* d_in, const int* in_sizes, int n_in,
                              void* d_out, int out_size)
{
    const float* x  = (const float*)d_in[0];
    const float* qw = (const float*)d_in[1];
    const float* kw = (const float*)d_in[2];
    const float* vw = (const float*)d_in[3];
    const float* ow = (const float*)d_in[4];

    const int M = in_sizes[0] / D_MODEL;
    const int B = M / S_LEN;
    const int W = D_MODEL * D_MODEL;

    void *pxh, *pxl, *pah, *pwh, *pwl;
    void *pqh, *pql, *pkh, *pkl, *pvh, *pct, *pst;
    cudaGetSymbolAddress(&pxh, g_xh);  cudaGetSymbolAddress(&pxl, g_xl);
    cudaGetSymbolAddress(&pah, g_aoh);
    cudaGetSymbolAddress(&pwh, g_wh);  cudaGetSymbolAddress(&pwl, g_wl);
    cudaGetSymbolAddress(&pqh, g_qh);  cudaGetSymbolAddress(&pql, g_ql);
    cudaGetSymbolAddress(&pkh, g_kh);  cudaGetSymbolAddress(&pkl, g_kl);
    cudaGetSymbolAddress(&pvh, g_vh);
    cudaGetSymbolAddress(&pct, g_ct);  cudaGetSymbolAddress(&pst, g_st);
    __half* xh = (__half*)pxh;  __half* xl = (__half*)pxl;
    __half* aoh = (__half*)pah;
    __half* wh = (__half*)pwh;  __half* wl = (__half*)pwl;
    __half* qhp = (__half*)pqh; __half* qlp = (__half*)pql;
    __half* khp = (__half*)pkh; __half* klp = (__half*)pkl;
    __half* vhp = (__half*)pvh;
    float* ct = (float*)pct; float* st = (float*)pst;

    int n4x = M * D_MODEL / 4;
    split_kernel<<<(n4x + 255) / 256, 256>>>(x, xh, xl, n4x);
    int n4w = W / 4;
    dim3 wgrid((n4w + 255) / 256, 4);
    split_w4<<<wgrid, 256>>>(qw, kw, vw, ow, wh, wl, n4w);
    rope_tab<<<(S_LEN * 32 + 255) / 256, 256>>>(ct, st);

    cudaFuncSetAttribute(gemm_qkv, cudaFuncAttributeMaxDynamicSharedMemorySize, G_SMEM_SZ);
    dim3 qkvgrid(D_MODEL / 128, M / 128, 3);
    gemm_qkv<<<qkvgrid, 256, G_SMEM_SZ>>>(xh, xl, wh, wl,
                                          qhp, qlp, khp, klp, vhp,
                                          ct, st, M, D_MODEL, D_MODEL);

    cudaFuncSetAttribute(flash_mma, cudaFuncAttributeMaxDynamicSharedMemorySize, F_SMEM);
    const int NB = NHEAD * B;
    flash_mma<<<2 * NB, 256, F_SMEM>>>(qhp, qlp, khp, klp, vhp, aoh, NB);

    cudaFuncSetAttribute(gemm_mma, cudaFuncAttributeMaxDynamicSharedMemorySize, G_SMEM_SZ);
    dim3 ggrid(D_MODEL / 128, M / 128);
    gemm_mma<<<ggrid, 256, G_SMEM_SZ>>>(aoh, wh + 3 * W, wl + 3 * W,
                                        (float*)d_out, M, D_MODEL, D_MODEL);
}